// round 14
// baseline (speedup 1.0000x reference)
#include <cuda_runtime.h>
#include <cuda_bf16.h>
#include <cstdint>

#define BB   8
#define NP   4096
#define KNN  20
#define CH   64
#define CEPS 1e-5f

// ---------------- scratch (static device globals; no allocation) ----------------
__device__ float g_xx   [BB * NP];
__device__ int   g_idxA [BB * NP * KNN];
__device__ int   g_idxB [BB * NP * KNN];
__device__ float g_ft   [BB * NP * CH];                 // transposed features [b][n][c]
__device__ float g_A    [BB * CH * NP];
__device__ float g_Bt   [BB * CH * NP];
__device__ float g_Y1   [(size_t)BB * CH * NP * KNN];   // 167.8 MB
__device__ float g_Y2   [(size_t)BB * CH * NP * KNN];   // 167.8 MB
__device__ float g_mx   [BB * CH * NP];                 // raw max-over-k of y2
__device__ float g_x1   [BB * CH * NP];
__device__ float g_x2   [BB * CH * NP];
__device__ float g_x3   [BB * CH * NP];
__device__ float g_st   [BB * CH * 2];                  // mean, rstd per (b, ch)
__device__ float g_ypart[BB * CH * 8 * 2];              // y1 stats block partials
__device__ float g_mpart[BB * CH * 16 * 2];             // maxk stats block partials
__device__ float g_Y    [(size_t)BB * 1024 * NP];       // 134 MB
__device__ float g_pool [BB * 1024];

// ---------------- packed f32x2 helpers ----------------
#define FMA_F32X2(d, a, b, c) \
    asm("fma.rn.f32x2 %0, %1, %2, %3;" : "=l"(d) : "l"(a), "l"(b), "l"(c))

__device__ __forceinline__ float f32x2_hsum(unsigned long long v) {
    float lo, hi;
    asm("mov.b64 {%0, %1}, %2;" : "=f"(lo), "=f"(hi) : "l"(v));
    return lo + hi;
}

// ---------------- register bubble insert (branch-free, fully unrolled) ----------------
#define BUBBLE_INSERT(dval, did)                                   \
    do {                                                           \
        float _v = (dval); int _id = (did);                        \
        _Pragma("unroll")                                          \
        for (int _k = 0; _k < KNN; _k++) {                         \
            if (_v > vals[_k]) {                                   \
                float _tv = vals[_k]; vals[_k] = _v; _v = _tv;     \
                int _ti = inds[_k]; inds[_k] = _id; _id = _ti;     \
            }                                                      \
        }                                                          \
    } while (0)

// ---------------- xx = sum_c f^2 ----------------
template<int C>
__global__ void xx_kernel(const float* __restrict__ f, float* __restrict__ xx) {
    int i = blockIdx.x * blockDim.x + threadIdx.x;
    if (i >= BB * NP) return;
    int b = i / NP, n = i % NP;
    const float* fb = f + (size_t)b * C * NP + n;
    float s = 0.f;
#pragma unroll
    for (int c = 0; c < C; c++) { float v = fb[(size_t)c * NP]; s += v * v; }
    xx[i] = s;
}

// ---------------- transpose: f[b][c][n] -> ft[b][n][c] ----------------
__global__ void transpose_kernel(const float* __restrict__ f, float* __restrict__ ft) {
    __shared__ float t[32][33];
    int b  = blockIdx.z;
    int c0 = blockIdx.y * 32;
    int n0 = blockIdx.x * 32;
    int tx = threadIdx.x, ty = threadIdx.y;
#pragma unroll
    for (int dy = 0; dy < 32; dy += 8)
        t[ty + dy][tx] = f[(size_t)b * CH * NP + (size_t)(c0 + ty + dy) * NP + n0 + tx];
    __syncthreads();
#pragma unroll
    for (int dy = 0; dy < 32; dy += 8)
        ft[(size_t)b * NP * CH + (size_t)(n0 + ty + dy) * CH + c0 + tx] = t[tx][ty + dy];
}

// ---------------- C=3 knn, split-scan: 2 threads per query ----------------
// Block: 128 threads = 64 queries x 2 halves. h=0 scans j%4 in {0,1}, h=1 scans {2,3}
// of every shared 64-candidate tile. Exact two-list merge reproduces top_k order.
__global__ __launch_bounds__(128)
void knn3_kernel(const float* __restrict__ f, const float* __restrict__ xx,
                 int* __restrict__ idxout) {
    const int TQ = 64;
    __shared__ float smc[TQ * 4];
    __shared__ float smxx[TQ];
    __shared__ float sv[128 * KNN];
    __shared__ int   si[128 * KNN];

    int b   = blockIdx.y;
    int tid = threadIdx.x;
    int h   = tid >> 6;           // half index
    int ql  = tid & 63;           // query slot
    int n   = blockIdx.x * TQ + ql;
    const float* fb = f + (size_t)b * 3 * NP;

    float q0 = fb[n], q1 = fb[NP + n], q2 = fb[2 * NP + n];

    float vals[KNN];
    int   inds[KNN];
#pragma unroll
    for (int k = 0; k < KNN; k++) { vals[k] = -3.4e38f; inds[k] = 0; }
    float minv = -3.4e38f;

    for (int m0 = 0; m0 < NP; m0 += TQ) {
        __syncthreads();
        for (int i = tid; i < TQ * 3; i += 128) {
            int c = i / TQ, j = i % TQ;
            smc[j * 4 + c] = fb[(size_t)c * NP + m0 + j];
        }
        if (tid < TQ) smxx[tid] = xx[b * NP + m0 + tid];
        __syncthreads();

#pragma unroll 2
        for (int jj = 0; jj < TQ / 4; jj++) {
            int j = jj * 4 + h * 2;
            const float* c0 = &smc[j * 4];
            const float* c1 = &smc[(j + 1) * 4];
            float d0 = 2.f * (q0*c0[0] + q1*c0[1] + q2*c0[2]) - smxx[j];
            float d1 = 2.f * (q0*c1[0] + q1*c1[1] + q2*c1[2]) - smxx[j + 1];
            if (d0 > minv) { BUBBLE_INSERT(d0, m0 + j);     minv = vals[KNN - 1]; }
            if (d1 > minv) { BUBBLE_INSERT(d1, m0 + j + 1); minv = vals[KNN - 1]; }
        }
    }

    // exact merge of the two half-lists
#pragma unroll
    for (int k = 0; k < KNN; k++) { sv[tid * KNN + k] = vals[k]; si[tid * KNN + k] = inds[k]; }
    __syncthreads();
    if (h == 0) {
        const float* va = &sv[ql * KNN];
        const float* vb = &sv[(ql + 64) * KNN];
        const int*   ja = &si[ql * KNN];
        const int*   jb = &si[(ql + 64) * KNN];
        int ia = 0, ib = 0;
        int* op = idxout + ((size_t)b * NP + n) * KNN;
#pragma unroll
        for (int k = 0; k < KNN; k++) {
            float A = va[ia], B = vb[ib];
            bool takeA = (A > B) || (A == B && ja[ia] < jb[ib]);
            if (takeA) { op[k] = ja[ia]; ia++; }
            else       { op[k] = jb[ib]; ib++; }
        }
    }
}

// ---------------- C=64 knn, split-scan + f32x2 + warm gate ----------------
__global__ __launch_bounds__(128)
void knn64_kernel(const float* __restrict__ ft, const float* __restrict__ xx,
                  const int* __restrict__ prev, int* __restrict__ idxout) {
    typedef unsigned long long ull;
    const int TQ = 64;
    const int CP = CH + 4;
    __shared__ __align__(16) float smc[TQ * CP];
    __shared__ float smxx[TQ];
    __shared__ float stau[128];
    __shared__ float sv[128 * KNN];
    __shared__ int   si[128 * KNN];

    int b   = blockIdx.y;
    int tid = threadIdx.x;
    int h   = tid >> 6;
    int ql  = tid & 63;
    int n   = blockIdx.x * TQ + ql;
    const float* ftb = ft + (size_t)b * NP * CH;
    const float* xxb = xx + b * NP;

    ull qp[CH / 2];
    {
        const ulonglong2* qs = (const ulonglong2*)(ftb + (size_t)n * CH);
#pragma unroll
        for (int i = 0; i < CH / 4; i++) { ulonglong2 t = qs[i]; qp[2*i] = t.x; qp[2*i+1] = t.y; }
    }

    float vals[KNN];
    int   inds[KNN];
#pragma unroll
    for (int k = 0; k < KNN; k++) { vals[k] = -3.4e38f; inds[k] = 0; }

    // ---- warm start: each half evaluates 10 of the 20 prev neighbors ----
    float tau = 3.4e38f;
    {
        const int* pi = prev + ((size_t)b * NP + n) * KNN + h * 10;
#pragma unroll 2
        for (int k = 0; k < 10; k++) {
            int m = pi[k];
            const ulonglong2* cs = (const ulonglong2*)(ftb + (size_t)m * CH);
            ull a0 = 0ull, a1 = 0ull;
#pragma unroll
            for (int i = 0; i < CH / 4; i++) {
                ulonglong2 t = cs[i];
                FMA_F32X2(a0, qp[2*i],   t.x, a0);
                FMA_F32X2(a1, qp[2*i+1], t.y, a1);
            }
            float d = 2.f * (f32x2_hsum(a0) + f32x2_hsum(a1)) - xxb[m];
            tau = fminf(tau, d);
        }
    }
    stau[tid] = tau;
    __syncthreads();
    tau = fminf(stau[ql], stau[ql + 64]);
    const float gate = tau - fabsf(tau) * 1e-4f - 1e-12f;
    float minv = gate;

    // ---- full scan, halves interleaved over shared tiles ----
    for (int m0 = 0; m0 < NP; m0 += TQ) {
        __syncthreads();
        for (int i = tid; i < TQ * (CH / 4); i += 128) {
            int j = i >> 4, c4 = i & 15;
            ((float4*)&smc[j * CP])[c4] = ((const float4*)(ftb + (size_t)(m0 + j) * CH))[c4];
        }
        if (tid < TQ) smxx[tid] = xxb[m0 + tid];
        __syncthreads();

        for (int jj = 0; jj < TQ / 4; jj++) {
            int j = jj * 4 + h * 2;
            const ulonglong2* c0 = (const ulonglong2*)&smc[j * CP];
            const ulonglong2* c1 = (const ulonglong2*)&smc[(j + 1) * CP];
            ull a00 = 0ull, a01 = 0ull, a10 = 0ull, a11 = 0ull;
#pragma unroll
            for (int i = 0; i < CH / 4; i++) {
                ulonglong2 t0 = c0[i], t1 = c1[i];
                FMA_F32X2(a00, qp[2*i],   t0.x, a00);
                FMA_F32X2(a01, qp[2*i+1], t0.y, a01);
                FMA_F32X2(a10, qp[2*i],   t1.x, a10);
                FMA_F32X2(a11, qp[2*i+1], t1.y, a11);
            }
            float d0 = 2.f * (f32x2_hsum(a00) + f32x2_hsum(a01)) - smxx[j];
            float d1 = 2.f * (f32x2_hsum(a10) + f32x2_hsum(a11)) - smxx[j + 1];
            if (d0 > minv) { BUBBLE_INSERT(d0, m0 + j);     minv = fmaxf(vals[KNN - 1], gate); }
            if (d1 > minv) { BUBBLE_INSERT(d1, m0 + j + 1); minv = fmaxf(vals[KNN - 1], gate); }
        }
    }

    // exact merge of the two half-lists
#pragma unroll
    for (int k = 0; k < KNN; k++) { sv[tid * KNN + k] = vals[k]; si[tid * KNN + k] = inds[k]; }
    __syncthreads();
    if (h == 0) {
        const float* va = &sv[ql * KNN];
        const float* vb = &sv[(ql + 64) * KNN];
        const int*   ja = &si[ql * KNN];
        const int*   jb = &si[(ql + 64) * KNN];
        int ia = 0, ib = 0;
        int* op = idxout + ((size_t)b * NP + n) * KNN;
#pragma unroll
        for (int k = 0; k < KNN; k++) {
            float A = va[ia], B = vb[ib];
            bool takeA = (A > B) || (A == B && ja[ia] < jb[ib]);
            if (takeA) { op[k] = ja[ia]; ia++; }
            else       { op[k] = jb[ib]; ib++; }
        }
    }
}

// ---------------- point transform: A = Wl@f, Bt = (Wr-Wl)@f ----------------
template<int C>
__global__ void pt_kernel(const float* __restrict__ f, const float* __restrict__ Wa,
                          float* __restrict__ A, float* __restrict__ Bt) {
    int i = blockIdx.x * blockDim.x + threadIdx.x;
    if (i >= BB * CH * NP) return;
    int n = i % NP, o = (i / NP) % CH, b = i / (NP * CH);
    const float* fb = f + (size_t)b * C * NP + n;
    const float* w  = Wa + o * 2 * C;
    float a = 0.f, bm = 0.f;
#pragma unroll
    for (int c = 0; c < C; c++) {
        float v = fb[(size_t)c * NP];
        a  += w[c] * v;
        bm += (w[C + c] - w[c]) * v;
    }
    A[i] = a; Bt[i] = bm;
}

// ---------------- y1 gather + fused stats partials (proven win) ----------------
__global__ void y1_fused_kernel(const float* __restrict__ A, const float* __restrict__ Bt,
                                const int* __restrict__ idx, float* __restrict__ Y1,
                                float* __restrict__ ypart) {
    __shared__ float sA[NP];                    // 16 KB: full A plane for this (b,o)
    int bo = blockIdx.y;
    int b  = bo / CH;
    for (int i = threadIdx.x; i < NP; i += blockDim.x)
        sA[i] = A[(size_t)bo * NP + i];
    __syncthreads();
    int n0 = blockIdx.x * 512;
    const int*  ib = idx + ((size_t)b * NP + n0) * KNN;
    const float* bt = Bt + (size_t)bo * NP + n0;
    float* y = Y1 + ((size_t)bo * NP + n0) * KNN;
    float s = 0.f, s2 = 0.f;
    for (int i = threadIdx.x; i < 512 * KNN; i += blockDim.x) {
        int nl = i / KNN;
        float v = sA[ib[i]] + bt[nl];
        y[i] = v;
        s += v; s2 += v * v;
    }
    __shared__ float sh[512];
    sh[threadIdx.x] = s; sh[256 + threadIdx.x] = s2;
    __syncthreads();
    for (int st = 128; st > 0; st >>= 1) {
        if (threadIdx.x < st) {
            sh[threadIdx.x]       += sh[threadIdx.x + st];
            sh[256 + threadIdx.x] += sh[256 + threadIdx.x + st];
        }
        __syncthreads();
    }
    if (threadIdx.x == 0) {
        ypart[(bo * 8 + blockIdx.x) * 2]     = sh[0];
        ypart[(bo * 8 + blockIdx.x) * 2 + 1] = sh[256];
    }
}

// ---------------- finalize y1 stats: 8 partials -> (m, r) ----------------
__global__ void yfin_kernel(const float* __restrict__ ypart, float* __restrict__ stats) {
    int ch = blockIdx.x * blockDim.x + threadIdx.x;
    if (ch >= BB * CH) return;
    float s = 0.f, s2 = 0.f;
#pragma unroll
    for (int i = 0; i < 8; i++) {
        s  += ypart[(ch * 8 + i) * 2];
        s2 += ypart[(ch * 8 + i) * 2 + 1];
    }
    const float P = (float)(NP * KNN);
    float m = s / P;
    float var = s2 / P - m * m;
    stats[ch * 2]     = m;
    stats[ch * 2 + 1] = rsqrtf(var + CEPS);
}

// ---------------- conv2: round-9 body (2 pts/thread, pure stores) ----------------
__global__ __launch_bounds__(128)
void conv2_kernel(const float* __restrict__ Y1, const float* __restrict__ Wb,
                  const float* __restrict__ stats, float* __restrict__ Y2) {
    const int P = NP * KNN;
    __shared__ float sWt[CH * CH];      // transposed: [c][o]
    __shared__ float sm[CH], sr[CH];
    int b = blockIdx.y;
    for (int i = threadIdx.x; i < CH * CH; i += 128) {
        int c = i >> 6, o = i & 63;
        sWt[c * CH + o] = Wb[o * CH + c];
    }
    if (threadIdx.x < CH) {
        sm[threadIdx.x] = stats[(b * CH + threadIdx.x) * 2];
        sr[threadIdx.x] = stats[(b * CH + threadIdx.x) * 2 + 1];
    }
    __syncthreads();
    int p0 = blockIdx.x * 256 + threadIdx.x;
    int p1 = p0 + 128;
    float acc0[CH], acc1[CH];
#pragma unroll
    for (int o = 0; o < CH; o++) { acc0[o] = 0.f; acc1[o] = 0.f; }
    const float* y1 = Y1 + (size_t)b * CH * P;
#pragma unroll 2
    for (int c = 0; c < CH; c++) {
        float v0 = y1[(size_t)c * P + p0];
        float v1 = y1[(size_t)c * P + p1];
        float m = sm[c], r = sr[c];
        v0 = (v0 - m) * r; v0 = v0 > 0.f ? v0 : 0.2f * v0;
        v1 = (v1 - m) * r; v1 = v1 > 0.f ? v1 : 0.2f * v1;
        const float4* w = (const float4*)&sWt[c * CH];
#pragma unroll
        for (int o4 = 0; o4 < 16; o4++) {
            float4 w4 = w[o4];
            acc0[4*o4+0] += w4.x * v0; acc1[4*o4+0] += w4.x * v1;
            acc0[4*o4+1] += w4.y * v0; acc1[4*o4+1] += w4.y * v1;
            acc0[4*o4+2] += w4.z * v0; acc1[4*o4+2] += w4.z * v1;
            acc0[4*o4+3] += w4.w * v0; acc1[4*o4+3] += w4.w * v1;
        }
    }
    float* y2 = Y2 + (size_t)b * CH * P;
#pragma unroll
    for (int o = 0; o < CH; o++) {
        y2[(size_t)o * P + p0] = acc0[o];
        y2[(size_t)o * P + p1] = acc1[o];
    }
}

// ---------------- maxk_fused: one pass over Y2 -> raw max + stats partials ----------------
__global__ __launch_bounds__(256)
void maxk_fused_kernel(const float* __restrict__ Y2, float* __restrict__ mxraw,
                       float* __restrict__ mpart) {
    int i = blockIdx.x * 256 + threadIdx.x;          // over B*CH*NP
    const float4* y = (const float4*)(Y2 + (size_t)i * KNN);
    float mx = -3.4e38f, s = 0.f, s2 = 0.f;
#pragma unroll
    for (int k4 = 0; k4 < 5; k4++) {
        float4 v = y[k4];
        mx = fmaxf(mx, fmaxf(fmaxf(v.x, v.y), fmaxf(v.z, v.w)));
        s  += (v.x + v.y) + (v.z + v.w);
        s2 += (v.x * v.x + v.y * v.y) + (v.z * v.z + v.w * v.w);
    }
    mxraw[i] = mx;
    __shared__ float sh[512];
    sh[threadIdx.x] = s; sh[256 + threadIdx.x] = s2;
    __syncthreads();
    for (int st = 128; st > 0; st >>= 1) {
        if (threadIdx.x < st) {
            sh[threadIdx.x]       += sh[threadIdx.x + st];
            sh[256 + threadIdx.x] += sh[256 + threadIdx.x + st];
        }
        __syncthreads();
    }
    if (threadIdx.x == 0) {
        mpart[blockIdx.x * 2]     = sh[0];
        mpart[blockIdx.x * 2 + 1] = sh[256];
    }
}

// ---------------- finalize maxk stats: 16 partials -> (m, r) ----------------
__global__ void mfin_kernel(const float* __restrict__ mpart, float* __restrict__ stats) {
    int ch = blockIdx.x * blockDim.x + threadIdx.x;
    if (ch >= BB * CH) return;
    float s = 0.f, s2 = 0.f;
#pragma unroll
    for (int i = 0; i < 16; i++) {
        s  += mpart[(ch * 16 + i) * 2];
        s2 += mpart[(ch * 16 + i) * 2 + 1];
    }
    const float P = (float)(NP * KNN);
    float m = s / P;
    float var = s2 / P - m * m;
    stats[ch * 2]     = m;
    stats[ch * 2 + 1] = rsqrtf(var + CEPS);
}

// ---------------- apply inorm+lrelu to the raw maxes (max commutes, r>0) ----------------
__global__ void apply_kernel(const float* __restrict__ mxraw, const float* __restrict__ stats,
                             float* __restrict__ xout) {
    int i = blockIdx.x * blockDim.x + threadIdx.x;
    if (i >= BB * CH * NP) return;
    int bo = i / NP;
    float m = stats[bo * 2], r = stats[bo * 2 + 1];
    float v = (mxraw[i] - m) * r;
    v = v > 0.f ? v : 0.2f * v;
    xout[i] = v;
}

// ---------------- final GEMM (round-9 exact): writes Y ----------------
__global__ __launch_bounds__(128)
void fgemm_kernel(const float* __restrict__ x1, const float* __restrict__ x2,
                  const float* __restrict__ x3, const float* __restrict__ Ws,
                  float* __restrict__ Y) {
    __shared__ float sWt[192 * 64];                // transposed [c][o], 48 KB
    int b  = blockIdx.z;
    int o0 = blockIdx.y * 64;
    int n0 = blockIdx.x * 256 + threadIdx.x;
    int n1 = n0 + 128;
    for (int i = threadIdx.x; i < 192 * 64; i += 128) {
        int c = i >> 6, o = i & 63;
        sWt[c * 64 + o] = Ws[(size_t)(o0 + o) * 192 + c];
    }
    __syncthreads();
    float acc0[64], acc1[64];
#pragma unroll
    for (int o = 0; o < 64; o++) { acc0[o] = 0.f; acc1[o] = 0.f; }
    const float* srcs[3] = { x1 + (size_t)b * CH * NP,
                             x2 + (size_t)b * CH * NP,
                             x3 + (size_t)b * CH * NP };
    for (int g = 0; g < 3; g++) {
        const float* s = srcs[g];
#pragma unroll 2
        for (int c = 0; c < 64; c++) {
            float v0 = s[(size_t)c * NP + n0];
            float v1 = s[(size_t)c * NP + n1];
            const float4* w = (const float4*)&sWt[(g * 64 + c) * 64];
#pragma unroll
            for (int o4 = 0; o4 < 16; o4++) {
                float4 w4 = w[o4];
                acc0[4*o4+0] += w4.x * v0; acc1[4*o4+0] += w4.x * v1;
                acc0[4*o4+1] += w4.y * v0; acc1[4*o4+1] += w4.y * v1;
                acc0[4*o4+2] += w4.z * v0; acc1[4*o4+2] += w4.z * v1;
                acc0[4*o4+3] += w4.w * v0; acc1[4*o4+3] += w4.w * v1;
            }
        }
    }
    float* y = Y + ((size_t)b * 1024 + o0) * NP;
#pragma unroll
    for (int o = 0; o < 64; o++) {
        y[(size_t)o * NP + n0] = acc0[o];
        y[(size_t)o * NP + n1] = acc1[o];
    }
}

// ---------------- fused head stats+pool: one block per (b,ch), single read of Y ----------------
__global__ __launch_bounds__(128)
void statspool_kernel(const float* __restrict__ Y, float* __restrict__ pool) {
    int ch = blockIdx.x;            // b*1024 + o
    const float4* y = (const float4*)(Y + (size_t)ch * NP);
    float s = 0.f, s2 = 0.f, mx = -3.4e38f;
    for (int i = threadIdx.x; i < NP / 4; i += 128) {
        float4 v = y[i];
        s  += (v.x + v.y) + (v.z + v.w);
        s2 += (v.x * v.x + v.y * v.y) + (v.z * v.z + v.w * v.w);
        mx  = fmaxf(mx, fmaxf(fmaxf(v.x, v.y), fmaxf(v.z, v.w)));
    }
    __shared__ float sh[384];
    sh[threadIdx.x] = s; sh[128 + threadIdx.x] = s2; sh[256 + threadIdx.x] = mx;
    __syncthreads();
    for (int st = 64; st > 0; st >>= 1) {
        if (threadIdx.x < st) {
            sh[threadIdx.x]       += sh[threadIdx.x + st];
            sh[128 + threadIdx.x] += sh[128 + threadIdx.x + st];
            sh[256 + threadIdx.x]  = fmaxf(sh[256 + threadIdx.x], sh[256 + threadIdx.x + st]);
        }
        __syncthreads();
    }
    if (threadIdx.x == 0) {
        float m   = sh[0] / (float)NP;
        float var = sh[128] / (float)NP - m * m;
        float r   = rsqrtf(var + CEPS);
        float v = (sh[256] - m) * r;   // max commutes with monotone affine map (r>0)
        v = v > 0.f ? v : 0.2f * v;
        pool[ch] = v;
    }
}

// ---------------- assemble output: [pool bcast | x1 | x2 | x3] ----------------
__global__ void out_kernel(const float* __restrict__ pool, const float* __restrict__ x1,
                           const float* __restrict__ x2, const float* __restrict__ x3,
                           float* __restrict__ out) {
    size_t i = (size_t)blockIdx.x * blockDim.x + threadIdx.x;
    const size_t total = (size_t)BB * 1216 * NP;
    if (i >= total) return;
    int n  = (int)(i % NP);
    int ch = (int)((i / NP) % 1216);
    int b  = (int)(i / ((size_t)NP * 1216));
    float v;
    if (ch < 1024) {
        v = pool[b * 1024 + ch];
    } else {
        int c2 = ch - 1024;
        const float* s = (c2 < 64) ? x1 : (c2 < 128 ? x2 : x3);
        v = s[((size_t)b * CH + (c2 & 63)) * NP + n];
    }
    out[i] = v;
}

// ---------------- conv tail shared by all layers ----------------
static void run_conv_tail(const float* Wb, const int* idxp, float* Ap, float* Btp,
                          float* Y1p, float* Y2p, float* stp, float* ypartp,
                          float* mpartp, float* mxp, float* xout) {
    y1_fused_kernel<<<dim3(NP / 512, BB * CH), 256>>>(Ap, Btp, idxp, Y1p, ypartp);
    yfin_kernel<<<2, 256>>>(ypartp, stp);
    conv2_kernel<<<dim3(NP * KNN / 256, BB), 128>>>(Y1p, Wb, stp, Y2p);
    maxk_fused_kernel<<<BB * CH * NP / 256, 256>>>(Y2p, mxp, mpartp);
    mfin_kernel<<<2, 256>>>(mpartp, stp);
    apply_kernel<<<(BB * CH * NP + 255) / 256, 256>>>(mxp, stp, xout);
}

extern "C" void kernel_launch(void* const* d_in, const int* in_sizes, int n_in,
                              void* d_out, int out_size) {
    const float* x   = (const float*)d_in[0];
    const float* W0a = (const float*)d_in[1];
    const float* W0b = (const float*)d_in[2];
    const float* W1a = (const float*)d_in[3];
    const float* W1b = (const float*)d_in[4];
    const float* W2a = (const float*)d_in[5];
    const float* W2b = (const float*)d_in[6];
    const float* Ws  = (const float*)d_in[7];
    float* out = (float*)d_out;

    float *xxp, *ftp, *Ap, *Btp, *Y1p, *Y2p, *mxp, *x1p, *x2p, *x3p, *stp;
    float *ypartp, *mpartp, *Yp, *poolp;
    int *idxAp, *idxBp;
    cudaGetSymbolAddress((void**)&xxp,    g_xx);
    cudaGetSymbolAddress((void**)&idxAp,  g_idxA);
    cudaGetSymbolAddress((void**)&idxBp,  g_idxB);
    cudaGetSymbolAddress((void**)&ftp,    g_ft);
    cudaGetSymbolAddress((void**)&Ap,     g_A);
    cudaGetSymbolAddress((void**)&Btp,    g_Bt);
    cudaGetSymbolAddress((void**)&Y1p,    g_Y1);
    cudaGetSymbolAddress((void**)&Y2p,    g_Y2);
    cudaGetSymbolAddress((void**)&mxp,    g_mx);
    cudaGetSymbolAddress((void**)&x1p,    g_x1);
    cudaGetSymbolAddress((void**)&x2p,    g_x2);
    cudaGetSymbolAddress((void**)&x3p,    g_x3);
    cudaGetSymbolAddress((void**)&stp,    g_st);
    cudaGetSymbolAddress((void**)&ypartp, g_ypart);
    cudaGetSymbolAddress((void**)&mpartp, g_mpart);
    cudaGetSymbolAddress((void**)&Yp,     g_Y);
    cudaGetSymbolAddress((void**)&poolp,  g_pool);

    // ---- layer 0 (C=3): knn on raw coords -> idxA ----
    xx_kernel<3><<<(BB * NP + 255) / 256, 256>>>(x, xxp);
    knn3_kernel<<<dim3(NP / 64, BB), 128>>>(x, xxp, idxAp);
    pt_kernel<3><<<(BB * CH * NP + 255) / 256, 256>>>(x, W0a, Ap, Btp);
    run_conv_tail(W0b, idxAp, Ap, Btp, Y1p, Y2p, stp, ypartp, mpartp, mxp, x1p);

    // ---- layer 1 (C=64): knn on x1, warm from idxA -> idxB ----
    xx_kernel<CH><<<(BB * NP + 255) / 256, 256>>>(x1p, xxp);
    transpose_kernel<<<dim3(NP / 32, CH / 32, BB), dim3(32, 8)>>>(x1p, ftp);
    knn64_kernel<<<dim3(NP / 64, BB), 128>>>(ftp, xxp, idxAp, idxBp);
    pt_kernel<CH><<<(BB * CH * NP + 255) / 256, 256>>>(x1p, W1a, Ap, Btp);
    run_conv_tail(W1b, idxBp, Ap, Btp, Y1p, Y2p, stp, ypartp, mpartp, mxp, x2p);

    // ---- layer 2 (C=64): knn on x2, warm from idxB -> idxA ----
    xx_kernel<CH><<<(BB * NP + 255) / 256, 256>>>(x2p, xxp);
    transpose_kernel<<<dim3(NP / 32, CH / 32, BB), dim3(32, 8)>>>(x2p, ftp);
    knn64_kernel<<<dim3(NP / 64, BB), 128>>>(ftp, xxp, idxBp, idxAp);
    pt_kernel<CH><<<(BB * CH * NP + 255) / 256, 256>>>(x2p, W2a, Ap, Btp);
    run_conv_tail(W2b, idxAp, Ap, Btp, Y1p, Y2p, stp, ypartp, mpartp, mxp, x3p);

    // ---- head: fgemm (round-9) -> fused stats+pool single pass ----
    fgemm_kernel<<<dim3(NP / 256, 1024 / 64, BB), 128>>>(x1p, x2p, x3p, Ws, Yp);
    statspool_kernel<<<BB * 1024, 128>>>(Yp, poolp);

    const size_t total = (size_t)BB * 1216 * NP;
    out_kernel<<<(unsigned)((total + 255) / 256), 256>>>(poolp, x1p, x2p, x3p, out);
}

// round 15
// speedup vs baseline: 1.0145x; 1.0145x over previous
#include <cuda_runtime.h>
#include <cuda_bf16.h>
#include <cstdint>

#define BB   8
#define NP   4096
#define KNN  20
#define CH   64
#define CEPS 1e-5f

// ---------------- scratch (static device globals; no allocation) ----------------
__device__ float g_xx   [BB * NP];
__device__ int   g_idxA [BB * NP * KNN];
__device__ int   g_idxB [BB * NP * KNN];
__device__ float g_ft   [BB * NP * CH];                 // transposed features [b][n][c]
__device__ float g_pv   [(size_t)BB * NP * 2 * KNN];    // knn partial top-K values
__device__ int   g_pi   [(size_t)BB * NP * 2 * KNN];    // knn partial top-K indices
__device__ float g_A    [BB * CH * NP];
__device__ float g_Bt   [BB * CH * NP];
__device__ float g_Y1   [(size_t)BB * CH * NP * KNN];   // 167.8 MB
__device__ float g_Y2   [(size_t)BB * CH * NP * KNN];   // 167.8 MB
__device__ float g_mx   [BB * CH * NP];                 // raw max-over-k of y2
__device__ float g_x1   [BB * CH * NP];
__device__ float g_x2   [BB * CH * NP];
__device__ float g_x3   [BB * CH * NP];
__device__ float g_st   [BB * CH * 2];                  // mean, rstd per (b, ch)
__device__ float g_ypart[BB * CH * 8 * 2];              // y1 stats block partials
__device__ float g_mpart[BB * CH * 16 * 2];             // maxk stats block partials
__device__ float g_Y    [(size_t)BB * 1024 * NP];       // 134 MB
__device__ float g_pool [BB * 1024];

// ---------------- packed f32x2 helpers ----------------
#define FMA_F32X2(d, a, b, c) \
    asm("fma.rn.f32x2 %0, %1, %2, %3;" : "=l"(d) : "l"(a), "l"(b), "l"(c))

__device__ __forceinline__ float f32x2_hsum(unsigned long long v) {
    float lo, hi;
    asm("mov.b64 {%0, %1}, %2;" : "=f"(lo), "=f"(hi) : "l"(v));
    return lo + hi;
}

// ---------------- register bubble insert (branch-free, fully unrolled) ----------------
#define BUBBLE_INSERT(dval, did)                                   \
    do {                                                           \
        float _v = (dval); int _id = (did);                        \
        _Pragma("unroll")                                          \
        for (int _k = 0; _k < KNN; _k++) {                         \
            if (_v > vals[_k]) {                                   \
                float _tv = vals[_k]; vals[_k] = _v; _v = _tv;     \
                int _ti = inds[_k]; inds[_k] = _id; _id = _ti;     \
            }                                                      \
        }                                                          \
    } while (0)

// ---------------- xx = sum_c f^2 ----------------
template<int C>
__global__ void xx_kernel(const float* __restrict__ f, float* __restrict__ xx) {
    int i = blockIdx.x * blockDim.x + threadIdx.x;
    if (i >= BB * NP) return;
    int b = i / NP, n = i % NP;
    const float* fb = f + (size_t)b * C * NP + n;
    float s = 0.f;
#pragma unroll
    for (int c = 0; c < C; c++) { float v = fb[(size_t)c * NP]; s += v * v; }
    xx[i] = s;
}

// ---------------- transpose: f[b][c][n] -> ft[b][n][c] ----------------
__global__ void transpose_kernel(const float* __restrict__ f, float* __restrict__ ft) {
    __shared__ float t[32][33];
    int b  = blockIdx.z;
    int c0 = blockIdx.y * 32;
    int n0 = blockIdx.x * 32;
    int tx = threadIdx.x, ty = threadIdx.y;
#pragma unroll
    for (int dy = 0; dy < 32; dy += 8)
        t[ty + dy][tx] = f[(size_t)b * CH * NP + (size_t)(c0 + ty + dy) * NP + n0 + tx];
    __syncthreads();
#pragma unroll
    for (int dy = 0; dy < 32; dy += 8)
        ft[(size_t)b * NP * CH + (size_t)(n0 + ty + dy) * CH + c0 + tx] = t[tx][ty + dy];
}

// ---------------- C=3 knn, candidate-split: each block scans half the range ----------------
// Inner loop identical to round-12; partial sorted top-20 written to pv/pi.
__global__ __launch_bounds__(128)
void knn3_part_kernel(const float* __restrict__ f, const float* __restrict__ xx,
                      float* __restrict__ pv, int* __restrict__ pi) {
    const int TQ = 128;
    const int CP = 4;
    __shared__ float smc[TQ * CP];
    __shared__ float smxx[TQ];
    int b     = blockIdx.z;
    int split = blockIdx.y;
    int n     = blockIdx.x * TQ + threadIdx.x;
    const float* fb = f + (size_t)b * 3 * NP;

    float q0 = fb[n], q1 = fb[NP + n], q2 = fb[2 * NP + n];

    float vals[KNN];
    int   inds[KNN];
#pragma unroll
    for (int k = 0; k < KNN; k++) { vals[k] = -3.4e38f; inds[k] = 0; }
    float minv = -3.4e38f;

    const int mBeg = split * (NP / 2), mEnd = mBeg + NP / 2;
    for (int m0 = mBeg; m0 < mEnd; m0 += TQ) {
        __syncthreads();
        for (int i = threadIdx.x; i < TQ * 3; i += TQ) {
            int c = i / TQ, j = i % TQ;
            smc[j * CP + c] = fb[(size_t)c * NP + m0 + j];
        }
        smxx[threadIdx.x] = xx[b * NP + m0 + threadIdx.x];
        __syncthreads();

        for (int j = 0; j < TQ; j += 2) {
            const float* c0 = &smc[j * CP];
            const float* c1 = &smc[(j + 1) * CP];
            float d0 = 2.f * (q0*c0[0] + q1*c0[1] + q2*c0[2]) - smxx[j];
            float d1 = 2.f * (q0*c1[0] + q1*c1[1] + q2*c1[2]) - smxx[j + 1];
            if (d0 > minv) { BUBBLE_INSERT(d0, m0 + j);     minv = vals[KNN - 1]; }
            if (d1 > minv) { BUBBLE_INSERT(d1, m0 + j + 1); minv = vals[KNN - 1]; }
        }
    }
    float* opv = pv + ((size_t)(b * NP + n) * 2 + split) * KNN;
    int*   opi = pi + ((size_t)(b * NP + n) * 2 + split) * KNN;
#pragma unroll
    for (int k = 0; k < KNN; k++) { opv[k] = vals[k]; opi[k] = inds[k]; }
}

// ---------------- C=64 knn, candidate-split + f32x2 + warm gate ----------------
__global__ __launch_bounds__(64)
void knn64_part_kernel(const float* __restrict__ ft, const float* __restrict__ xx,
                       const int* __restrict__ prev,
                       float* __restrict__ pv, int* __restrict__ pi) {
    typedef unsigned long long ull;
    const int TQ = 64;
    const int CP = CH + 4;
    __shared__ __align__(16) float smc[TQ * CP];
    __shared__ float smxx[TQ];

    int b     = blockIdx.z;
    int split = blockIdx.y;
    int n     = blockIdx.x * TQ + threadIdx.x;
    const float* ftb = ft + (size_t)b * NP * CH;
    const float* xxb = xx + b * NP;

    ull qp[CH / 2];
    {
        const ulonglong2* qs = (const ulonglong2*)(ftb + (size_t)n * CH);
#pragma unroll
        for (int i = 0; i < CH / 4; i++) { ulonglong2 t = qs[i]; qp[2*i] = t.x; qp[2*i+1] = t.y; }
    }

    float vals[KNN];
    int   inds[KNN];
#pragma unroll
    for (int k = 0; k < KNN; k++) { vals[k] = -3.4e38f; inds[k] = 0; }

    // warm start: full 20 prev neighbors -> tau is a lower bound on true d20
    float tau = 3.4e38f;
    {
        const int* pprev = prev + ((size_t)b * NP + n) * KNN;
#pragma unroll 4
        for (int k = 0; k < KNN; k++) {
            int m = pprev[k];
            const ulonglong2* cs = (const ulonglong2*)(ftb + (size_t)m * CH);
            ull a0 = 0ull, a1 = 0ull;
#pragma unroll
            for (int i = 0; i < CH / 4; i++) {
                ulonglong2 t = cs[i];
                FMA_F32X2(a0, qp[2*i],   t.x, a0);
                FMA_F32X2(a1, qp[2*i+1], t.y, a1);
            }
            float d = 2.f * (f32x2_hsum(a0) + f32x2_hsum(a1)) - xxb[m];
            tau = fminf(tau, d);
        }
    }
    const float gate = tau - fabsf(tau) * 1e-4f - 1e-12f;
    float minv = gate;

    const int mBeg = split * (NP / 2), mEnd = mBeg + NP / 2;
    for (int m0 = mBeg; m0 < mEnd; m0 += TQ) {
        __syncthreads();
        for (int i = threadIdx.x; i < TQ * (CH / 4); i += 64) {
            int j = i >> 4, c4 = i & 15;
            ((float4*)&smc[j * CP])[c4] = ((const float4*)(ftb + (size_t)(m0 + j) * CH))[c4];
        }
        smxx[threadIdx.x] = xxb[m0 + threadIdx.x];
        __syncthreads();

        for (int j = 0; j < TQ; j += 2) {
            const ulonglong2* c0 = (const ulonglong2*)&smc[j * CP];
            const ulonglong2* c1 = (const ulonglong2*)&smc[(j + 1) * CP];
            ull a00 = 0ull, a01 = 0ull, a10 = 0ull, a11 = 0ull;
#pragma unroll
            for (int i = 0; i < CH / 4; i++) {
                ulonglong2 t0 = c0[i], t1 = c1[i];
                FMA_F32X2(a00, qp[2*i],   t0.x, a00);
                FMA_F32X2(a01, qp[2*i+1], t0.y, a01);
                FMA_F32X2(a10, qp[2*i],   t1.x, a10);
                FMA_F32X2(a11, qp[2*i+1], t1.y, a11);
            }
            float d0 = 2.f * (f32x2_hsum(a00) + f32x2_hsum(a01)) - smxx[j];
            float d1 = 2.f * (f32x2_hsum(a10) + f32x2_hsum(a11)) - smxx[j + 1];
            if (d0 > minv) { BUBBLE_INSERT(d0, m0 + j);     minv = fmaxf(vals[KNN - 1], gate); }
            if (d1 > minv) { BUBBLE_INSERT(d1, m0 + j + 1); minv = fmaxf(vals[KNN - 1], gate); }
        }
    }
    float* opv = pv + ((size_t)(b * NP + n) * 2 + split) * KNN;
    int*   opi = pi + ((size_t)(b * NP + n) * 2 + split) * KNN;
#pragma unroll
    for (int k = 0; k < KNN; k++) { opv[k] = vals[k]; opi[k] = inds[k]; }
}

// ---------------- merge two sorted partial top-20 lists (exact top_k order) ----------------
// Part 0 owns lower candidate indices; comparator (A>B)||(A==B && iA<iB) reproduces
// the unsplit insertion order exactly.
__global__ void knn_merge_kernel(const float* __restrict__ pv, const int* __restrict__ pi,
                                 int* __restrict__ idxout) {
    int q = blockIdx.x * 256 + threadIdx.x;          // over BB*NP
    if (q >= BB * NP) return;
    const float* va = pv + (size_t)q * 2 * KNN;
    const float* vb = va + KNN;
    const int*   ja = pi + (size_t)q * 2 * KNN;
    const int*   jb = ja + KNN;
    int ia = 0, ib = 0;
    int* op = idxout + (size_t)q * KNN;
#pragma unroll
    for (int k = 0; k < KNN; k++) {
        float A = va[ia], B = vb[ib];
        bool takeA = (A > B) || (A == B && ja[ia] < jb[ib]);
        if (takeA) { op[k] = ja[ia]; ia++; }
        else       { op[k] = jb[ib]; ib++; }
    }
}

// ---------------- point transform: A = Wl@f, Bt = (Wr-Wl)@f ----------------
template<int C>
__global__ void pt_kernel(const float* __restrict__ f, const float* __restrict__ Wa,
                          float* __restrict__ A, float* __restrict__ Bt) {
    int i = blockIdx.x * blockDim.x + threadIdx.x;
    if (i >= BB * CH * NP) return;
    int n = i % NP, o = (i / NP) % CH, b = i / (NP * CH);
    const float* fb = f + (size_t)b * C * NP + n;
    const float* w  = Wa + o * 2 * C;
    float a = 0.f, bm = 0.f;
#pragma unroll
    for (int c = 0; c < C; c++) {
        float v = fb[(size_t)c * NP];
        a  += w[c] * v;
        bm += (w[C + c] - w[c]) * v;
    }
    A[i] = a; Bt[i] = bm;
}

// ---------------- y1 gather + fused stats partials (proven win) ----------------
__global__ void y1_fused_kernel(const float* __restrict__ A, const float* __restrict__ Bt,
                                const int* __restrict__ idx, float* __restrict__ Y1,
                                float* __restrict__ ypart) {
    __shared__ float sA[NP];                    // 16 KB: full A plane for this (b,o)
    int bo = blockIdx.y;
    int b  = bo / CH;
    for (int i = threadIdx.x; i < NP; i += blockDim.x)
        sA[i] = A[(size_t)bo * NP + i];
    __syncthreads();
    int n0 = blockIdx.x * 512;
    const int*  ib = idx + ((size_t)b * NP + n0) * KNN;
    const float* bt = Bt + (size_t)bo * NP + n0;
    float* y = Y1 + ((size_t)bo * NP + n0) * KNN;
    float s = 0.f, s2 = 0.f;
    for (int i = threadIdx.x; i < 512 * KNN; i += blockDim.x) {
        int nl = i / KNN;
        float v = sA[ib[i]] + bt[nl];
        y[i] = v;
        s += v; s2 += v * v;
    }
    __shared__ float sh[512];
    sh[threadIdx.x] = s; sh[256 + threadIdx.x] = s2;
    __syncthreads();
    for (int st = 128; st > 0; st >>= 1) {
        if (threadIdx.x < st) {
            sh[threadIdx.x]       += sh[threadIdx.x + st];
            sh[256 + threadIdx.x] += sh[256 + threadIdx.x + st];
        }
        __syncthreads();
    }
    if (threadIdx.x == 0) {
        ypart[(bo * 8 + blockIdx.x) * 2]     = sh[0];
        ypart[(bo * 8 + blockIdx.x) * 2 + 1] = sh[256];
    }
}

// ---------------- finalize y1 stats: 8 partials -> (m, r) ----------------
__global__ void yfin_kernel(const float* __restrict__ ypart, float* __restrict__ stats) {
    int ch = blockIdx.x * blockDim.x + threadIdx.x;
    if (ch >= BB * CH) return;
    float s = 0.f, s2 = 0.f;
#pragma unroll
    for (int i = 0; i < 8; i++) {
        s  += ypart[(ch * 8 + i) * 2];
        s2 += ypart[(ch * 8 + i) * 2 + 1];
    }
    const float P = (float)(NP * KNN);
    float m = s / P;
    float var = s2 / P - m * m;
    stats[ch * 2]     = m;
    stats[ch * 2 + 1] = rsqrtf(var + CEPS);
}

// ---------------- conv2: round-9 body (2 pts/thread, pure stores) ----------------
__global__ __launch_bounds__(128)
void conv2_kernel(const float* __restrict__ Y1, const float* __restrict__ Wb,
                  const float* __restrict__ stats, float* __restrict__ Y2) {
    const int P = NP * KNN;
    __shared__ float sWt[CH * CH];      // transposed: [c][o]
    __shared__ float sm[CH], sr[CH];
    int b = blockIdx.y;
    for (int i = threadIdx.x; i < CH * CH; i += 128) {
        int c = i >> 6, o = i & 63;
        sWt[c * CH + o] = Wb[o * CH + c];
    }
    if (threadIdx.x < CH) {
        sm[threadIdx.x] = stats[(b * CH + threadIdx.x) * 2];
        sr[threadIdx.x] = stats[(b * CH + threadIdx.x) * 2 + 1];
    }
    __syncthreads();
    int p0 = blockIdx.x * 256 + threadIdx.x;
    int p1 = p0 + 128;
    float acc0[CH], acc1[CH];
#pragma unroll
    for (int o = 0; o < CH; o++) { acc0[o] = 0.f; acc1[o] = 0.f; }
    const float* y1 = Y1 + (size_t)b * CH * P;
#pragma unroll 2
    for (int c = 0; c < CH; c++) {
        float v0 = y1[(size_t)c * P + p0];
        float v1 = y1[(size_t)c * P + p1];
        float m = sm[c], r = sr[c];
        v0 = (v0 - m) * r; v0 = v0 > 0.f ? v0 : 0.2f * v0;
        v1 = (v1 - m) * r; v1 = v1 > 0.f ? v1 : 0.2f * v1;
        const float4* w = (const float4*)&sWt[c * CH];
#pragma unroll
        for (int o4 = 0; o4 < 16; o4++) {
            float4 w4 = w[o4];
            acc0[4*o4+0] += w4.x * v0; acc1[4*o4+0] += w4.x * v1;
            acc0[4*o4+1] += w4.y * v0; acc1[4*o4+1] += w4.y * v1;
            acc0[4*o4+2] += w4.z * v0; acc1[4*o4+2] += w4.z * v1;
            acc0[4*o4+3] += w4.w * v0; acc1[4*o4+3] += w4.w * v1;
        }
    }
    float* y2 = Y2 + (size_t)b * CH * P;
#pragma unroll
    for (int o = 0; o < CH; o++) {
        y2[(size_t)o * P + p0] = acc0[o];
        y2[(size_t)o * P + p1] = acc1[o];
    }
}

// ---------------- maxk_fused: one pass over Y2 -> raw max + stats partials ----------------
__global__ __launch_bounds__(256)
void maxk_fused_kernel(const float* __restrict__ Y2, float* __restrict__ mxraw,
                       float* __restrict__ mpart) {
    int i = blockIdx.x * 256 + threadIdx.x;          // over B*CH*NP
    const float4* y = (const float4*)(Y2 + (size_t)i * KNN);
    float mx = -3.4e38f, s = 0.f, s2 = 0.f;
#pragma unroll
    for (int k4 = 0; k4 < 5; k4++) {
        float4 v = y[k4];
        mx = fmaxf(mx, fmaxf(fmaxf(v.x, v.y), fmaxf(v.z, v.w)));
        s  += (v.x + v.y) + (v.z + v.w);
        s2 += (v.x * v.x + v.y * v.y) + (v.z * v.z + v.w * v.w);
    }
    mxraw[i] = mx;
    __shared__ float sh[512];
    sh[threadIdx.x] = s; sh[256 + threadIdx.x] = s2;
    __syncthreads();
    for (int st = 128; st > 0; st >>= 1) {
        if (threadIdx.x < st) {
            sh[threadIdx.x]       += sh[threadIdx.x + st];
            sh[256 + threadIdx.x] += sh[256 + threadIdx.x + st];
        }
        __syncthreads();
    }
    if (threadIdx.x == 0) {
        mpart[blockIdx.x * 2]     = sh[0];
        mpart[blockIdx.x * 2 + 1] = sh[256];
    }
}

// ---------------- finalize maxk stats: 16 partials -> (m, r) ----------------
__global__ void mfin_kernel(const float* __restrict__ mpart, float* __restrict__ stats) {
    int ch = blockIdx.x * blockDim.x + threadIdx.x;
    if (ch >= BB * CH) return;
    float s = 0.f, s2 = 0.f;
#pragma unroll
    for (int i = 0; i < 16; i++) {
        s  += mpart[(ch * 16 + i) * 2];
        s2 += mpart[(ch * 16 + i) * 2 + 1];
    }
    const float P = (float)(NP * KNN);
    float m = s / P;
    float var = s2 / P - m * m;
    stats[ch * 2]     = m;
    stats[ch * 2 + 1] = rsqrtf(var + CEPS);
}

// ---------------- apply inorm+lrelu to the raw maxes (max commutes, r>0) ----------------
__global__ void apply_kernel(const float* __restrict__ mxraw, const float* __restrict__ stats,
                             float* __restrict__ xout) {
    int i = blockIdx.x * blockDim.x + threadIdx.x;
    if (i >= BB * CH * NP) return;
    int bo = i / NP;
    float m = stats[bo * 2], r = stats[bo * 2 + 1];
    float v = (mxraw[i] - m) * r;
    v = v > 0.f ? v : 0.2f * v;
    xout[i] = v;
}

// ---------------- final GEMM (round-9 exact): writes Y ----------------
__global__ __launch_bounds__(128)
void fgemm_kernel(const float* __restrict__ x1, const float* __restrict__ x2,
                  const float* __restrict__ x3, const float* __restrict__ Ws,
                  float* __restrict__ Y) {
    __shared__ float sWt[192 * 64];                // transposed [c][o], 48 KB
    int b  = blockIdx.z;
    int o0 = blockIdx.y * 64;
    int n0 = blockIdx.x * 256 + threadIdx.x;
    int n1 = n0 + 128;
    for (int i = threadIdx.x; i < 192 * 64; i += 128) {
        int c = i >> 6, o = i & 63;
        sWt[c * 64 + o] = Ws[(size_t)(o0 + o) * 192 + c];
    }
    __syncthreads();
    float acc0[64], acc1[64];
#pragma unroll
    for (int o = 0; o < 64; o++) { acc0[o] = 0.f; acc1[o] = 0.f; }
    const float* srcs[3] = { x1 + (size_t)b * CH * NP,
                             x2 + (size_t)b * CH * NP,
                             x3 + (size_t)b * CH * NP };
    for (int g = 0; g < 3; g++) {
        const float* s = srcs[g];
#pragma unroll 2
        for (int c = 0; c < 64; c++) {
            float v0 = s[(size_t)c * NP + n0];
            float v1 = s[(size_t)c * NP + n1];
            const float4* w = (const float4*)&sWt[(g * 64 + c) * 64];
#pragma unroll
            for (int o4 = 0; o4 < 16; o4++) {
                float4 w4 = w[o4];
                acc0[4*o4+0] += w4.x * v0; acc1[4*o4+0] += w4.x * v1;
                acc0[4*o4+1] += w4.y * v0; acc1[4*o4+1] += w4.y * v1;
                acc0[4*o4+2] += w4.z * v0; acc1[4*o4+2] += w4.z * v1;
                acc0[4*o4+3] += w4.w * v0; acc1[4*o4+3] += w4.w * v1;
            }
        }
    }
    float* y = Y + ((size_t)b * 1024 + o0) * NP;
#pragma unroll
    for (int o = 0; o < 64; o++) {
        y[(size_t)o * NP + n0] = acc0[o];
        y[(size_t)o * NP + n1] = acc1[o];
    }
}

// ---------------- fused head stats+pool: one block per (b,ch), single read of Y ----------------
__global__ __launch_bounds__(128)
void statspool_kernel(const float* __restrict__ Y, float* __restrict__ pool) {
    int ch = blockIdx.x;            // b*1024 + o
    const float4* y = (const float4*)(Y + (size_t)ch * NP);
    float s = 0.f, s2 = 0.f, mx = -3.4e38f;
    for (int i = threadIdx.x; i < NP / 4; i += 128) {
        float4 v = y[i];
        s  += (v.x + v.y) + (v.z + v.w);
        s2 += (v.x * v.x + v.y * v.y) + (v.z * v.z + v.w * v.w);
        mx  = fmaxf(mx, fmaxf(fmaxf(v.x, v.y), fmaxf(v.z, v.w)));
    }
    __shared__ float sh[384];
    sh[threadIdx.x] = s; sh[128 + threadIdx.x] = s2; sh[256 + threadIdx.x] = mx;
    __syncthreads();
    for (int st = 64; st > 0; st >>= 1) {
        if (threadIdx.x < st) {
            sh[threadIdx.x]       += sh[threadIdx.x + st];
            sh[128 + threadIdx.x] += sh[128 + threadIdx.x + st];
            sh[256 + threadIdx.x]  = fmaxf(sh[256 + threadIdx.x], sh[256 + threadIdx.x + st]);
        }
        __syncthreads();
    }
    if (threadIdx.x == 0) {
        float m   = sh[0] / (float)NP;
        float var = sh[128] / (float)NP - m * m;
        float r   = rsqrtf(var + CEPS);
        float v = (sh[256] - m) * r;   // max commutes with monotone affine map (r>0)
        v = v > 0.f ? v : 0.2f * v;
        pool[ch] = v;
    }
}

// ---------------- assemble output: [pool bcast | x1 | x2 | x3] ----------------
__global__ void out_kernel(const float* __restrict__ pool, const float* __restrict__ x1,
                           const float* __restrict__ x2, const float* __restrict__ x3,
                           float* __restrict__ out) {
    size_t i = (size_t)blockIdx.x * blockDim.x + threadIdx.x;
    const size_t total = (size_t)BB * 1216 * NP;
    if (i >= total) return;
    int n  = (int)(i % NP);
    int ch = (int)((i / NP) % 1216);
    int b  = (int)(i / ((size_t)NP * 1216));
    float v;
    if (ch < 1024) {
        v = pool[b * 1024 + ch];
    } else {
        int c2 = ch - 1024;
        const float* s = (c2 < 64) ? x1 : (c2 < 128 ? x2 : x3);
        v = s[((size_t)b * CH + (c2 & 63)) * NP + n];
    }
    out[i] = v;
}

// ---------------- conv tail shared by all layers ----------------
static void run_conv_tail(const float* Wb, const int* idxp, float* Ap, float* Btp,
                          float* Y1p, float* Y2p, float* stp, float* ypartp,
                          float* mpartp, float* mxp, float* xout) {
    y1_fused_kernel<<<dim3(NP / 512, BB * CH), 256>>>(Ap, Btp, idxp, Y1p, ypartp);
    yfin_kernel<<<2, 256>>>(ypartp, stp);
    conv2_kernel<<<dim3(NP * KNN / 256, BB), 128>>>(Y1p, Wb, stp, Y2p);
    maxk_fused_kernel<<<BB * CH * NP / 256, 256>>>(Y2p, mxp, mpartp);
    mfin_kernel<<<2, 256>>>(mpartp, stp);
    apply_kernel<<<(BB * CH * NP + 255) / 256, 256>>>(mxp, stp, xout);
}

extern "C" void kernel_launch(void* const* d_in, const int* in_sizes, int n_in,
                              void* d_out, int out_size) {
    const float* x   = (const float*)d_in[0];
    const float* W0a = (const float*)d_in[1];
    const float* W0b = (const float*)d_in[2];
    const float* W1a = (const float*)d_in[3];
    const float* W1b = (const float*)d_in[4];
    const float* W2a = (const float*)d_in[5];
    const float* W2b = (const float*)d_in[6];
    const float* Ws  = (const float*)d_in[7];
    float* out = (float*)d_out;

    float *xxp, *ftp, *pvp, *Ap, *Btp, *Y1p, *Y2p, *mxp, *x1p, *x2p, *x3p, *stp;
    float *ypartp, *mpartp, *Yp, *poolp;
    int *idxAp, *idxBp, *pip;
    cudaGetSymbolAddress((void**)&xxp,    g_xx);
    cudaGetSymbolAddress((void**)&idxAp,  g_idxA);
    cudaGetSymbolAddress((void**)&idxBp,  g_idxB);
    cudaGetSymbolAddress((void**)&ftp,    g_ft);
    cudaGetSymbolAddress((void**)&pvp,    g_pv);
    cudaGetSymbolAddress((void**)&pip,    g_pi);
    cudaGetSymbolAddress((void**)&Ap,     g_A);
    cudaGetSymbolAddress((void**)&Btp,    g_Bt);
    cudaGetSymbolAddress((void**)&Y1p,    g_Y1);
    cudaGetSymbolAddress((void**)&Y2p,    g_Y2);
    cudaGetSymbolAddress((void**)&mxp,    g_mx);
    cudaGetSymbolAddress((void**)&x1p,    g_x1);
    cudaGetSymbolAddress((void**)&x2p,    g_x2);
    cudaGetSymbolAddress((void**)&x3p,    g_x3);
    cudaGetSymbolAddress((void**)&stp,    g_st);
    cudaGetSymbolAddress((void**)&ypartp, g_ypart);
    cudaGetSymbolAddress((void**)&mpartp, g_mpart);
    cudaGetSymbolAddress((void**)&Yp,     g_Y);
    cudaGetSymbolAddress((void**)&poolp,  g_pool);

    const int MERGE_BLKS = (BB * NP + 255) / 256;

    // ---- layer 0 (C=3): split knn on raw coords -> idxA ----
    xx_kernel<3><<<(BB * NP + 255) / 256, 256>>>(x, xxp);
    knn3_part_kernel<<<dim3(NP / 128, 2, BB), 128>>>(x, xxp, pvp, pip);
    knn_merge_kernel<<<MERGE_BLKS, 256>>>(pvp, pip, idxAp);
    pt_kernel<3><<<(BB * CH * NP + 255) / 256, 256>>>(x, W0a, Ap, Btp);
    run_conv_tail(W0b, idxAp, Ap, Btp, Y1p, Y2p, stp, ypartp, mpartp, mxp, x1p);

    // ---- layer 1 (C=64): split knn on x1, warm from idxA -> idxB ----
    xx_kernel<CH><<<(BB * NP + 255) / 256, 256>>>(x1p, xxp);
    transpose_kernel<<<dim3(NP / 32, CH / 32, BB), dim3(32, 8)>>>(x1p, ftp);
    knn64_part_kernel<<<dim3(NP / 64, 2, BB), 64>>>(ftp, xxp, idxAp, pvp, pip);
    knn_merge_kernel<<<MERGE_BLKS, 256>>>(pvp, pip, idxBp);
    pt_kernel<CH><<<(BB * CH * NP + 255) / 256, 256>>>(x1p, W1a, Ap, Btp);
    run_conv_tail(W1b, idxBp, Ap, Btp, Y1p, Y2p, stp, ypartp, mpartp, mxp, x2p);

    // ---- layer 2 (C=64): split knn on x2, warm from idxB -> idxA ----
    xx_kernel<CH><<<(BB * NP + 255) / 256, 256>>>(x2p, xxp);
    transpose_kernel<<<dim3(NP / 32, CH / 32, BB), dim3(32, 8)>>>(x2p, ftp);
    knn64_part_kernel<<<dim3(NP / 64, 2, BB), 64>>>(ftp, xxp, idxBp, pvp, pip);
    knn_merge_kernel<<<MERGE_BLKS, 256>>>(pvp, pip, idxAp);
    pt_kernel<CH><<<(BB * CH * NP + 255) / 256, 256>>>(x2p, W2a, Ap, Btp);
    run_conv_tail(W2b, idxAp, Ap, Btp, Y1p, Y2p, stp, ypartp, mpartp, mxp, x3p);

    // ---- head: fgemm (round-9) -> fused stats+pool single pass ----
    fgemm_kernel<<<dim3(NP / 256, 1024 / 64, BB), 128>>>(x1p, x2p, x3p, Ws, Yp);
    statspool_kernel<<<BB * 1024, 128>>>(Yp, poolp);

    const size_t total = (size_t)BB * 1216 * NP;
    out_kernel<<<(unsigned)((total + 255) / 256), 256>>>(poolp, x1p, x2p, x3p, out);
}

// round 16
// speedup vs baseline: 1.1508x; 1.1343x over previous
#include <cuda_runtime.h>
#include <cuda_bf16.h>
#include <cstdint>

#define BB   8
#define NP   4096
#define KNN  20
#define CH   64
#define CEPS 1e-5f
#define QCAP 8

// ---------------- scratch (static device globals; no allocation) ----------------
__device__ float g_xx   [BB * NP];
__device__ int   g_idxA [BB * NP * KNN];
__device__ int   g_idxB [BB * NP * KNN];
__device__ float g_ft   [BB * NP * CH];                 // transposed features [b][n][c]
__device__ float g_A    [BB * CH * NP];
__device__ float g_Bt   [BB * CH * NP];
__device__ float g_Y1   [(size_t)BB * CH * NP * KNN];   // 167.8 MB
__device__ float g_Y2   [(size_t)BB * CH * NP * KNN];   // 167.8 MB
__device__ float g_mx   [BB * CH * NP];                 // raw max-over-k of y2
__device__ float g_x1   [BB * CH * NP];
__device__ float g_x2   [BB * CH * NP];
__device__ float g_x3   [BB * CH * NP];
__device__ float g_st   [BB * CH * 2];                  // mean, rstd per (b, ch)
__device__ float g_ypart[BB * CH * 8 * 2];              // y1 stats block partials
__device__ float g_mpart[BB * CH * 16 * 2];             // maxk stats block partials
__device__ float g_Y    [(size_t)BB * 1024 * NP];       // 134 MB
__device__ float g_pool [BB * 1024];

// ---------------- packed f32x2 helpers ----------------
#define FMA_F32X2(d, a, b, c) \
    asm("fma.rn.f32x2 %0, %1, %2, %3;" : "=l"(d) : "l"(a), "l"(b), "l"(c))

__device__ __forceinline__ float f32x2_hsum(unsigned long long v) {
    float lo, hi;
    asm("mov.b64 {%0, %1}, %2;" : "=f"(lo), "=f"(hi) : "l"(v));
    return lo + hi;
}

// ---------------- register bubble insert (branch-free, fully unrolled) ----------------
#define BUBBLE_INSERT(dval, did)                                   \
    do {                                                           \
        float _v = (dval); int _id = (did);                        \
        _Pragma("unroll")                                          \
        for (int _k = 0; _k < KNN; _k++) {                         \
            if (_v > vals[_k]) {                                   \
                float _tv = vals[_k]; vals[_k] = _v; _v = _tv;     \
                int _ti = inds[_k]; inds[_k] = _id; _id = _ti;     \
            }                                                      \
        }                                                          \
    } while (0)

// ---------------- xx = sum_c f^2 ----------------
template<int C>
__global__ void xx_kernel(const float* __restrict__ f, float* __restrict__ xx) {
    int i = blockIdx.x * blockDim.x + threadIdx.x;
    if (i >= BB * NP) return;
    int b = i / NP, n = i % NP;
    const float* fb = f + (size_t)b * C * NP + n;
    float s = 0.f;
#pragma unroll
    for (int c = 0; c < C; c++) { float v = fb[(size_t)c * NP]; s += v * v; }
    xx[i] = s;
}

// ---------------- transpose: f[b][c][n] -> ft[b][n][c] ----------------
__global__ void transpose_kernel(const float* __restrict__ f, float* __restrict__ ft) {
    __shared__ float t[32][33];
    int b  = blockIdx.z;
    int c0 = blockIdx.y * 32;
    int n0 = blockIdx.x * 32;
    int tx = threadIdx.x, ty = threadIdx.y;
#pragma unroll
    for (int dy = 0; dy < 32; dy += 8)
        t[ty + dy][tx] = f[(size_t)b * CH * NP + (size_t)(c0 + ty + dy) * NP + n0 + tx];
    __syncthreads();
#pragma unroll
    for (int dy = 0; dy < 32; dy += 8)
        ft[(size_t)b * NP * CH + (size_t)(n0 + ty + dy) * CH + c0 + tx] = t[tx][ty + dy];
}

// ---------------- C=3 knn with queued (deferred) inserts ----------------
// Passing candidates go to a per-lane smem FIFO; the 110-instr register bubble
// runs only when some lane's queue fills (ballot), killing warp-convergence cost.
// Queue preserves scan order -> final top-20 identical to immediate insertion.
__global__ __launch_bounds__(128)
void knn3_kernel(const float* __restrict__ f, const float* __restrict__ xx,
                 int* __restrict__ idxout) {
    const int TQ = 128;
    const int CP = 4;
    __shared__ float smc[TQ * CP];
    __shared__ float smxx[TQ];
    __shared__ float sqd[128 * QCAP];
    __shared__ int   sqi[128 * QCAP];
    int b = blockIdx.y;
    int n = blockIdx.x * TQ + threadIdx.x;
    const float* fb = f + (size_t)b * 3 * NP;
    const int qbase = threadIdx.x * QCAP;

    float q0 = fb[n], q1 = fb[NP + n], q2 = fb[2 * NP + n];

    float vals[KNN];
    int   inds[KNN];
#pragma unroll
    for (int k = 0; k < KNN; k++) { vals[k] = -3.4e38f; inds[k] = 0; }
    float minv = -3.4e38f;
    int qn = 0;

    for (int m0 = 0; m0 < NP; m0 += TQ) {
        __syncthreads();
        for (int i = threadIdx.x; i < TQ * 3; i += TQ) {
            int c = i / TQ, j = i % TQ;
            smc[j * CP + c] = fb[(size_t)c * NP + m0 + j];
        }
        smxx[threadIdx.x] = xx[b * NP + m0 + threadIdx.x];
        __syncthreads();

        for (int j = 0; j < TQ; j += 2) {
            const float* c0 = &smc[j * CP];
            const float* c1 = &smc[(j + 1) * CP];
            float d0 = 2.f * (q0*c0[0] + q1*c0[1] + q2*c0[2]) - smxx[j];
            float d1 = 2.f * (q0*c1[0] + q1*c1[1] + q2*c1[2]) - smxx[j + 1];
            if (d0 > minv) { sqd[qbase + qn] = d0; sqi[qbase + qn] = m0 + j;     qn++; }
            if (d1 > minv) { sqd[qbase + qn] = d1; sqi[qbase + qn] = m0 + j + 1; qn++; }
            if (__ballot_sync(0xffffffffu, qn >= QCAP - 2)) {
                for (int e = 0; e < qn; e++) {
                    float v = sqd[qbase + e];
                    if (v > minv) {
                        BUBBLE_INSERT(v, sqi[qbase + e]);
                        minv = vals[KNN - 1];
                    }
                }
                qn = 0;
            }
        }
    }
    // final drain
    for (int e = 0; e < qn; e++) {
        float v = sqd[qbase + e];
        if (v > minv) { BUBBLE_INSERT(v, sqi[qbase + e]); minv = vals[KNN - 1]; }
    }
    int* op = idxout + ((size_t)b * NP + n) * KNN;
#pragma unroll
    for (int k = 0; k < KNN; k++) op[k] = inds[k];
}

// ---------------- C=64 knn: f32x2 dots + warm gate + queued inserts ----------------
__global__ __launch_bounds__(64)
void knn64_kernel(const float* __restrict__ ft, const float* __restrict__ xx,
                  const int* __restrict__ prev, int* __restrict__ idxout) {
    typedef unsigned long long ull;
    const int TQ = 64;
    const int CP = CH + 4;
    __shared__ __align__(16) float smc[TQ * CP];
    __shared__ float smxx[TQ];
    __shared__ float sqd[64 * QCAP];
    __shared__ int   sqi[64 * QCAP];

    int b = blockIdx.y;
    int n = blockIdx.x * TQ + threadIdx.x;
    const float* ftb = ft + (size_t)b * NP * CH;
    const float* xxb = xx + b * NP;
    const int qbase = threadIdx.x * QCAP;

    ull qp[CH / 2];
    {
        const ulonglong2* qs = (const ulonglong2*)(ftb + (size_t)n * CH);
#pragma unroll
        for (int i = 0; i < CH / 4; i++) { ulonglong2 t = qs[i]; qp[2*i] = t.x; qp[2*i+1] = t.y; }
    }

    float vals[KNN];
    int   inds[KNN];
#pragma unroll
    for (int k = 0; k < KNN; k++) { vals[k] = -3.4e38f; inds[k] = 0; }

    // warm start: tau = min over prev-layer neighbors' distances (exact lower bound)
    float tau = 3.4e38f;
    {
        const int* pi = prev + ((size_t)b * NP + n) * KNN;
#pragma unroll 4
        for (int k = 0; k < KNN; k++) {
            int m = pi[k];
            const ulonglong2* cs = (const ulonglong2*)(ftb + (size_t)m * CH);
            ull a0 = 0ull, a1 = 0ull;
#pragma unroll
            for (int i = 0; i < CH / 4; i++) {
                ulonglong2 t = cs[i];
                FMA_F32X2(a0, qp[2*i],   t.x, a0);
                FMA_F32X2(a1, qp[2*i+1], t.y, a1);
            }
            float d = 2.f * (f32x2_hsum(a0) + f32x2_hsum(a1)) - xxb[m];
            tau = fminf(tau, d);
        }
    }
    const float gate = tau - fabsf(tau) * 1e-4f - 1e-12f;
    float minv = gate;
    int qn = 0;

    for (int m0 = 0; m0 < NP; m0 += TQ) {
        __syncthreads();
        for (int i = threadIdx.x; i < TQ * (CH / 4); i += 64) {
            int j = i >> 4, c4 = i & 15;
            ((float4*)&smc[j * CP])[c4] = ((const float4*)(ftb + (size_t)(m0 + j) * CH))[c4];
        }
        smxx[threadIdx.x] = xxb[m0 + threadIdx.x];
        __syncthreads();

        for (int j = 0; j < TQ; j += 2) {
            const ulonglong2* c0 = (const ulonglong2*)&smc[j * CP];
            const ulonglong2* c1 = (const ulonglong2*)&smc[(j + 1) * CP];
            ull a00 = 0ull, a01 = 0ull, a10 = 0ull, a11 = 0ull;
#pragma unroll
            for (int i = 0; i < CH / 4; i++) {
                ulonglong2 t0 = c0[i], t1 = c1[i];
                FMA_F32X2(a00, qp[2*i],   t0.x, a00);
                FMA_F32X2(a01, qp[2*i+1], t0.y, a01);
                FMA_F32X2(a10, qp[2*i],   t1.x, a10);
                FMA_F32X2(a11, qp[2*i+1], t1.y, a11);
            }
            float d0 = 2.f * (f32x2_hsum(a00) + f32x2_hsum(a01)) - smxx[j];
            float d1 = 2.f * (f32x2_hsum(a10) + f32x2_hsum(a11)) - smxx[j + 1];
            if (d0 > minv) { sqd[qbase + qn] = d0; sqi[qbase + qn] = m0 + j;     qn++; }
            if (d1 > minv) { sqd[qbase + qn] = d1; sqi[qbase + qn] = m0 + j + 1; qn++; }
            if (__ballot_sync(0xffffffffu, qn >= QCAP - 2)) {
                for (int e = 0; e < qn; e++) {
                    float v = sqd[qbase + e];
                    if (v > minv) {
                        BUBBLE_INSERT(v, sqi[qbase + e]);
                        minv = fmaxf(vals[KNN - 1], gate);
                    }
                }
                qn = 0;
            }
        }
    }
    // final drain
    for (int e = 0; e < qn; e++) {
        float v = sqd[qbase + e];
        if (v > minv) { BUBBLE_INSERT(v, sqi[qbase + e]); minv = fmaxf(vals[KNN - 1], gate); }
    }
    int* op = idxout + ((size_t)b * NP + n) * KNN;
#pragma unroll
    for (int k = 0; k < KNN; k++) op[k] = inds[k];
}

// ---------------- point transform: A = Wl@f, Bt = (Wr-Wl)@f ----------------
template<int C>
__global__ void pt_kernel(const float* __restrict__ f, const float* __restrict__ Wa,
                          float* __restrict__ A, float* __restrict__ Bt) {
    int i = blockIdx.x * blockDim.x + threadIdx.x;
    if (i >= BB * CH * NP) return;
    int n = i % NP, o = (i / NP) % CH, b = i / (NP * CH);
    const float* fb = f + (size_t)b * C * NP + n;
    const float* w  = Wa + o * 2 * C;
    float a = 0.f, bm = 0.f;
#pragma unroll
    for (int c = 0; c < C; c++) {
        float v = fb[(size_t)c * NP];
        a  += w[c] * v;
        bm += (w[C + c] - w[c]) * v;
    }
    A[i] = a; Bt[i] = bm;
}

// ---------------- y1 gather + fused stats partials (proven win) ----------------
__global__ void y1_fused_kernel(const float* __restrict__ A, const float* __restrict__ Bt,
                                const int* __restrict__ idx, float* __restrict__ Y1,
                                float* __restrict__ ypart) {
    __shared__ float sA[NP];                    // 16 KB: full A plane for this (b,o)
    int bo = blockIdx.y;
    int b  = bo / CH;
    for (int i = threadIdx.x; i < NP; i += blockDim.x)
        sA[i] = A[(size_t)bo * NP + i];
    __syncthreads();
    int n0 = blockIdx.x * 512;
    const int*  ib = idx + ((size_t)b * NP + n0) * KNN;
    const float* bt = Bt + (size_t)bo * NP + n0;
    float* y = Y1 + ((size_t)bo * NP + n0) * KNN;
    float s = 0.f, s2 = 0.f;
    for (int i = threadIdx.x; i < 512 * KNN; i += blockDim.x) {
        int nl = i / KNN;
        float v = sA[ib[i]] + bt[nl];
        y[i] = v;
        s += v; s2 += v * v;
    }
    __shared__ float sh[512];
    sh[threadIdx.x] = s; sh[256 + threadIdx.x] = s2;
    __syncthreads();
    for (int st = 128; st > 0; st >>= 1) {
        if (threadIdx.x < st) {
            sh[threadIdx.x]       += sh[threadIdx.x + st];
            sh[256 + threadIdx.x] += sh[256 + threadIdx.x + st];
        }
        __syncthreads();
    }
    if (threadIdx.x == 0) {
        ypart[(bo * 8 + blockIdx.x) * 2]     = sh[0];
        ypart[(bo * 8 + blockIdx.x) * 2 + 1] = sh[256];
    }
}

// ---------------- finalize y1 stats: 8 partials -> (m, r) ----------------
__global__ void yfin_kernel(const float* __restrict__ ypart, float* __restrict__ stats) {
    int ch = blockIdx.x * blockDim.x + threadIdx.x;
    if (ch >= BB * CH) return;
    float s = 0.f, s2 = 0.f;
#pragma unroll
    for (int i = 0; i < 8; i++) {
        s  += ypart[(ch * 8 + i) * 2];
        s2 += ypart[(ch * 8 + i) * 2 + 1];
    }
    const float P = (float)(NP * KNN);
    float m = s / P;
    float var = s2 / P - m * m;
    stats[ch * 2]     = m;
    stats[ch * 2 + 1] = rsqrtf(var + CEPS);
}

// ---------------- conv2: round-9 body (2 pts/thread, pure stores) ----------------
__global__ __launch_bounds__(128)
void conv2_kernel(const float* __restrict__ Y1, const float* __restrict__ Wb,
                  const float* __restrict__ stats, float* __restrict__ Y2) {
    const int P = NP * KNN;
    __shared__ float sWt[CH * CH];      // transposed: [c][o]
    __shared__ float sm[CH], sr[CH];
    int b = blockIdx.y;
    for (int i = threadIdx.x; i < CH * CH; i += 128) {
        int c = i >> 6, o = i & 63;
        sWt[c * CH + o] = Wb[o * CH + c];
    }
    if (threadIdx.x < CH) {
        sm[threadIdx.x] = stats[(b * CH + threadIdx.x) * 2];
        sr[threadIdx.x] = stats[(b * CH + threadIdx.x) * 2 + 1];
    }
    __syncthreads();
    int p0 = blockIdx.x * 256 + threadIdx.x;
    int p1 = p0 + 128;
    float acc0[CH], acc1[CH];
#pragma unroll
    for (int o = 0; o < CH; o++) { acc0[o] = 0.f; acc1[o] = 0.f; }
    const float* y1 = Y1 + (size_t)b * CH * P;
#pragma unroll 2
    for (int c = 0; c < CH; c++) {
        float v0 = y1[(size_t)c * P + p0];
        float v1 = y1[(size_t)c * P + p1];
        float m = sm[c], r = sr[c];
        v0 = (v0 - m) * r; v0 = v0 > 0.f ? v0 : 0.2f * v0;
        v1 = (v1 - m) * r; v1 = v1 > 0.f ? v1 : 0.2f * v1;
        const float4* w = (const float4*)&sWt[c * CH];
#pragma unroll
        for (int o4 = 0; o4 < 16; o4++) {
            float4 w4 = w[o4];
            acc0[4*o4+0] += w4.x * v0; acc1[4*o4+0] += w4.x * v1;
            acc0[4*o4+1] += w4.y * v0; acc1[4*o4+1] += w4.y * v1;
            acc0[4*o4+2] += w4.z * v0; acc1[4*o4+2] += w4.z * v1;
            acc0[4*o4+3] += w4.w * v0; acc1[4*o4+3] += w4.w * v1;
        }
    }
    float* y2 = Y2 + (size_t)b * CH * P;
#pragma unroll
    for (int o = 0; o < CH; o++) {
        y2[(size_t)o * P + p0] = acc0[o];
        y2[(size_t)o * P + p1] = acc1[o];
    }
}

// ---------------- maxk_fused: one pass over Y2 -> raw max + stats partials ----------------
__global__ __launch_bounds__(256)
void maxk_fused_kernel(const float* __restrict__ Y2, float* __restrict__ mxraw,
                       float* __restrict__ mpart) {
    int i = blockIdx.x * 256 + threadIdx.x;          // over B*CH*NP
    const float4* y = (const float4*)(Y2 + (size_t)i * KNN);
    float mx = -3.4e38f, s = 0.f, s2 = 0.f;
#pragma unroll
    for (int k4 = 0; k4 < 5; k4++) {
        float4 v = y[k4];
        mx = fmaxf(mx, fmaxf(fmaxf(v.x, v.y), fmaxf(v.z, v.w)));
        s  += (v.x + v.y) + (v.z + v.w);
        s2 += (v.x * v.x + v.y * v.y) + (v.z * v.z + v.w * v.w);
    }
    mxraw[i] = mx;
    __shared__ float sh[512];
    sh[threadIdx.x] = s; sh[256 + threadIdx.x] = s2;
    __syncthreads();
    for (int st = 128; st > 0; st >>= 1) {
        if (threadIdx.x < st) {
            sh[threadIdx.x]       += sh[threadIdx.x + st];
            sh[256 + threadIdx.x] += sh[256 + threadIdx.x + st];
        }
        __syncthreads();
    }
    if (threadIdx.x == 0) {
        mpart[blockIdx.x * 2]     = sh[0];
        mpart[blockIdx.x * 2 + 1] = sh[256];
    }
}

// ---------------- finalize maxk stats: 16 partials -> (m, r) ----------------
__global__ void mfin_kernel(const float* __restrict__ mpart, float* __restrict__ stats) {
    int ch = blockIdx.x * blockDim.x + threadIdx.x;
    if (ch >= BB * CH) return;
    float s = 0.f, s2 = 0.f;
#pragma unroll
    for (int i = 0; i < 16; i++) {
        s  += mpart[(ch * 16 + i) * 2];
        s2 += mpart[(ch * 16 + i) * 2 + 1];
    }
    const float P = (float)(NP * KNN);
    float m = s / P;
    float var = s2 / P - m * m;
    stats[ch * 2]     = m;
    stats[ch * 2 + 1] = rsqrtf(var + CEPS);
}

// ---------------- apply inorm+lrelu to the raw maxes (max commutes, r>0) ----------------
__global__ void apply_kernel(const float* __restrict__ mxraw, const float* __restrict__ stats,
                             float* __restrict__ xout) {
    int i = blockIdx.x * blockDim.x + threadIdx.x;
    if (i >= BB * CH * NP) return;
    int bo = i / NP;
    float m = stats[bo * 2], r = stats[bo * 2 + 1];
    float v = (mxraw[i] - m) * r;
    v = v > 0.f ? v : 0.2f * v;
    xout[i] = v;
}

// ---------------- final GEMM (round-9 exact): writes Y ----------------
__global__ __launch_bounds__(128)
void fgemm_kernel(const float* __restrict__ x1, const float* __restrict__ x2,
                  const float* __restrict__ x3, const float* __restrict__ Ws,
                  float* __restrict__ Y) {
    __shared__ float sWt[192 * 64];                // transposed [c][o], 48 KB
    int b  = blockIdx.z;
    int o0 = blockIdx.y * 64;
    int n0 = blockIdx.x * 256 + threadIdx.x;
    int n1 = n0 + 128;
    for (int i = threadIdx.x; i < 192 * 64; i += 128) {
        int c = i >> 6, o = i & 63;
        sWt[c * 64 + o] = Ws[(size_t)(o0 + o) * 192 + c];
    }
    __syncthreads();
    float acc0[64], acc1[64];
#pragma unroll
    for (int o = 0; o < 64; o++) { acc0[o] = 0.f; acc1[o] = 0.f; }
    const float* srcs[3] = { x1 + (size_t)b * CH * NP,
                             x2 + (size_t)b * CH * NP,
                             x3 + (size_t)b * CH * NP };
    for (int g = 0; g < 3; g++) {
        const float* s = srcs[g];
#pragma unroll 2
        for (int c = 0; c < 64; c++) {
            float v0 = s[(size_t)c * NP + n0];
            float v1 = s[(size_t)c * NP + n1];
            const float4* w = (const float4*)&sWt[(g * 64 + c) * 64];
#pragma unroll
            for (int o4 = 0; o4 < 16; o4++) {
                float4 w4 = w[o4];
                acc0[4*o4+0] += w4.x * v0; acc1[4*o4+0] += w4.x * v1;
                acc0[4*o4+1] += w4.y * v0; acc1[4*o4+1] += w4.y * v1;
                acc0[4*o4+2] += w4.z * v0; acc1[4*o4+2] += w4.z * v1;
                acc0[4*o4+3] += w4.w * v0; acc1[4*o4+3] += w4.w * v1;
            }
        }
    }
    float* y = Y + ((size_t)b * 1024 + o0) * NP;
#pragma unroll
    for (int o = 0; o < 64; o++) {
        y[(size_t)o * NP + n0] = acc0[o];
        y[(size_t)o * NP + n1] = acc1[o];
    }
}

// ---------------- fused head stats+pool: one block per (b,ch), single read of Y ----------------
__global__ __launch_bounds__(128)
void statspool_kernel(const float* __restrict__ Y, float* __restrict__ pool) {
    int ch = blockIdx.x;            // b*1024 + o
    const float4* y = (const float4*)(Y + (size_t)ch * NP);
    float s = 0.f, s2 = 0.f, mx = -3.4e38f;
    for (int i = threadIdx.x; i < NP / 4; i += 128) {
        float4 v = y[i];
        s  += (v.x + v.y) + (v.z + v.w);
        s2 += (v.x * v.x + v.y * v.y) + (v.z * v.z + v.w * v.w);
        mx  = fmaxf(mx, fmaxf(fmaxf(v.x, v.y), fmaxf(v.z, v.w)));
    }
    __shared__ float sh[384];
    sh[threadIdx.x] = s; sh[128 + threadIdx.x] = s2; sh[256 + threadIdx.x] = mx;
    __syncthreads();
    for (int st = 64; st > 0; st >>= 1) {
        if (threadIdx.x < st) {
            sh[threadIdx.x]       += sh[threadIdx.x + st];
            sh[128 + threadIdx.x] += sh[128 + threadIdx.x + st];
            sh[256 + threadIdx.x]  = fmaxf(sh[256 + threadIdx.x], sh[256 + threadIdx.x + st]);
        }
        __syncthreads();
    }
    if (threadIdx.x == 0) {
        float m   = sh[0] / (float)NP;
        float var = sh[128] / (float)NP - m * m;
        float r   = rsqrtf(var + CEPS);
        float v = (sh[256] - m) * r;   // max commutes with monotone affine map (r>0)
        v = v > 0.f ? v : 0.2f * v;
        pool[ch] = v;
    }
}

// ---------------- assemble output: [pool bcast | x1 | x2 | x3] ----------------
__global__ void out_kernel(const float* __restrict__ pool, const float* __restrict__ x1,
                           const float* __restrict__ x2, const float* __restrict__ x3,
                           float* __restrict__ out) {
    size_t i = (size_t)blockIdx.x * blockDim.x + threadIdx.x;
    const size_t total = (size_t)BB * 1216 * NP;
    if (i >= total) return;
    int n  = (int)(i % NP);
    int ch = (int)((i / NP) % 1216);
    int b  = (int)(i / ((size_t)NP * 1216));
    float v;
    if (ch < 1024) {
        v = pool[b * 1024 + ch];
    } else {
        int c2 = ch - 1024;
        const float* s = (c2 < 64) ? x1 : (c2 < 128 ? x2 : x3);
        v = s[((size_t)b * CH + (c2 & 63)) * NP + n];
    }
    out[i] = v;
}

// ---------------- conv tail shared by all layers ----------------
static void run_conv_tail(const float* Wb, const int* idxp, float* Ap, float* Btp,
                          float* Y1p, float* Y2p, float* stp, float* ypartp,
                          float* mpartp, float* mxp, float* xout) {
    y1_fused_kernel<<<dim3(NP / 512, BB * CH), 256>>>(Ap, Btp, idxp, Y1p, ypartp);
    yfin_kernel<<<2, 256>>>(ypartp, stp);
    conv2_kernel<<<dim3(NP * KNN / 256, BB), 128>>>(Y1p, Wb, stp, Y2p);
    maxk_fused_kernel<<<BB * CH * NP / 256, 256>>>(Y2p, mxp, mpartp);
    mfin_kernel<<<2, 256>>>(mpartp, stp);
    apply_kernel<<<(BB * CH * NP + 255) / 256, 256>>>(mxp, stp, xout);
}

extern "C" void kernel_launch(void* const* d_in, const int* in_sizes, int n_in,
                              void* d_out, int out_size) {
    const float* x   = (const float*)d_in[0];
    const float* W0a = (const float*)d_in[1];
    const float* W0b = (const float*)d_in[2];
    const float* W1a = (const float*)d_in[3];
    const float* W1b = (const float*)d_in[4];
    const float* W2a = (const float*)d_in[5];
    const float* W2b = (const float*)d_in[6];
    const float* Ws  = (const float*)d_in[7];
    float* out = (float*)d_out;

    float *xxp, *ftp, *Ap, *Btp, *Y1p, *Y2p, *mxp, *x1p, *x2p, *x3p, *stp;
    float *ypartp, *mpartp, *Yp, *poolp;
    int *idxAp, *idxBp;
    cudaGetSymbolAddress((void**)&xxp,    g_xx);
    cudaGetSymbolAddress((void**)&idxAp,  g_idxA);
    cudaGetSymbolAddress((void**)&idxBp,  g_idxB);
    cudaGetSymbolAddress((void**)&ftp,    g_ft);
    cudaGetSymbolAddress((void**)&Ap,     g_A);
    cudaGetSymbolAddress((void**)&Btp,    g_Bt);
    cudaGetSymbolAddress((void**)&Y1p,    g_Y1);
    cudaGetSymbolAddress((void**)&Y2p,    g_Y2);
    cudaGetSymbolAddress((void**)&mxp,    g_mx);
    cudaGetSymbolAddress((void**)&x1p,    g_x1);
    cudaGetSymbolAddress((void**)&x2p,    g_x2);
    cudaGetSymbolAddress((void**)&x3p,    g_x3);
    cudaGetSymbolAddress((void**)&stp,    g_st);
    cudaGetSymbolAddress((void**)&ypartp, g_ypart);
    cudaGetSymbolAddress((void**)&mpartp, g_mpart);
    cudaGetSymbolAddress((void**)&Yp,     g_Y);
    cudaGetSymbolAddress((void**)&poolp,  g_pool);

    // ---- layer 0 (C=3): knn on raw coords -> idxA ----
    xx_kernel<3><<<(BB * NP + 255) / 256, 256>>>(x, xxp);
    knn3_kernel<<<dim3(NP / 128, BB), 128>>>(x, xxp, idxAp);
    pt_kernel<3><<<(BB * CH * NP + 255) / 256, 256>>>(x, W0a, Ap, Btp);
    run_conv_tail(W0b, idxAp, Ap, Btp, Y1p, Y2p, stp, ypartp, mpartp, mxp, x1p);

    // ---- layer 1 (C=64): knn on x1, warm from idxA -> idxB ----
    xx_kernel<CH><<<(BB * NP + 255) / 256, 256>>>(x1p, xxp);
    transpose_kernel<<<dim3(NP / 32, CH / 32, BB), dim3(32, 8)>>>(x1p, ftp);
    knn64_kernel<<<dim3(NP / 64, BB), 64>>>(ftp, xxp, idxAp, idxBp);
    pt_kernel<CH><<<(BB * CH * NP + 255) / 256, 256>>>(x1p, W1a, Ap, Btp);
    run_conv_tail(W1b, idxBp, Ap, Btp, Y1p, Y2p, stp, ypartp, mpartp, mxp, x2p);

    // ---- layer 2 (C=64): knn on x2, warm from idxB -> idxA ----
    xx_kernel<CH><<<(BB * NP + 255) / 256, 256>>>(x2p, xxp);
    transpose_kernel<<<dim3(NP / 32, CH / 32, BB), dim3(32, 8)>>>(x2p, ftp);
    knn64_kernel<<<dim3(NP / 64, BB), 64>>>(ftp, xxp, idxBp, idxAp);
    pt_kernel<CH><<<(BB * CH * NP + 255) / 256, 256>>>(x2p, W2a, Ap, Btp);
    run_conv_tail(W2b, idxAp, Ap, Btp, Y1p, Y2p, stp, ypartp, mpartp, mxp, x3p);

    // ---- head: fgemm (round-9) -> fused stats+pool single pass ----
    fgemm_kernel<<<dim3(NP / 256, 1024 / 64, BB), 128>>>(x1p, x2p, x3p, Ws, Yp);
    statspool_kernel<<<BB * 1024, 128>>>(Yp, poolp);

    const size_t total = (size_t)BB * 1216 * NP;
    out_kernel<<<(unsigned)((total + 255) / 256), 256>>>(poolp, x1p, x2p, x3p, out);
}

// round 17
// speedup vs baseline: 1.2074x; 1.0492x over previous
#include <cuda_runtime.h>
#include <cuda_bf16.h>
#include <cstdint>

#define BB   8
#define NP   4096
#define KNN  20
#define CH   64
#define CEPS 1e-5f
#define QCAP 8
#define QC64 12

// ---------------- scratch (static device globals; no allocation) ----------------
__device__ float g_xx   [BB * NP];
__device__ int   g_idxA [BB * NP * KNN];
__device__ int   g_idxB [BB * NP * KNN];
__device__ float g_ft   [BB * NP * CH];                 // transposed features [b][n][c]
__device__ float g_A    [BB * CH * NP];
__device__ float g_Bt   [BB * CH * NP];
__device__ float g_Y1   [(size_t)BB * CH * NP * KNN];   // 167.8 MB
__device__ float g_Y2   [(size_t)BB * CH * NP * KNN];   // 167.8 MB
__device__ float g_mx   [BB * CH * NP];                 // raw max-over-k of y2
__device__ float g_x1   [BB * CH * NP];
__device__ float g_x2   [BB * CH * NP];
__device__ float g_x3   [BB * CH * NP];
__device__ float g_st   [BB * CH * 2];                  // mean, rstd per (b, ch)
__device__ float g_ypart[BB * CH * 8 * 2];              // y1 stats block partials
__device__ float g_mpart[BB * CH * 16 * 2];             // maxk stats block partials
__device__ float g_Y    [(size_t)BB * 1024 * NP];       // 134 MB
__device__ float g_pool [BB * 1024];

// ---------------- packed f32x2 helpers ----------------
typedef unsigned long long ull;

#define FMA_F32X2(d, a, b, c) \
    asm("fma.rn.f32x2 %0, %1, %2, %3;" : "=l"(d) : "l"(a), "l"(b), "l"(c))

#define PACK2(dst, x) \
    asm("mov.b64 %0, {%1, %1};" : "=l"(dst) : "f"(x))

#define UNPACK2(lo, hi, v) \
    asm("mov.b64 {%0, %1}, %2;" : "=f"(lo), "=f"(hi) : "l"(v))

__device__ __forceinline__ float f32x2_hsum(ull v) {
    float lo, hi;
    asm("mov.b64 {%0, %1}, %2;" : "=f"(lo), "=f"(hi) : "l"(v));
    return lo + hi;
}

// ---------------- register bubble insert (branch-free, fully unrolled) ----------------
#define BUBBLE_INSERT(dval, did)                                   \
    do {                                                           \
        float _v = (dval); int _id = (did);                        \
        _Pragma("unroll")                                          \
        for (int _k = 0; _k < KNN; _k++) {                         \
            if (_v > vals[_k]) {                                   \
                float _tv = vals[_k]; vals[_k] = _v; _v = _tv;     \
                int _ti = inds[_k]; inds[_k] = _id; _id = _ti;     \
            }                                                      \
        }                                                          \
    } while (0)

// ---------------- xx = sum_c f^2 ----------------
template<int C>
__global__ void xx_kernel(const float* __restrict__ f, float* __restrict__ xx) {
    int i = blockIdx.x * blockDim.x + threadIdx.x;
    if (i >= BB * NP) return;
    int b = i / NP, n = i % NP;
    const float* fb = f + (size_t)b * C * NP + n;
    float s = 0.f;
#pragma unroll
    for (int c = 0; c < C; c++) { float v = fb[(size_t)c * NP]; s += v * v; }
    xx[i] = s;
}

// ---------------- transpose: f[b][c][n] -> ft[b][n][c] ----------------
__global__ void transpose_kernel(const float* __restrict__ f, float* __restrict__ ft) {
    __shared__ float t[32][33];
    int b  = blockIdx.z;
    int c0 = blockIdx.y * 32;
    int n0 = blockIdx.x * 32;
    int tx = threadIdx.x, ty = threadIdx.y;
#pragma unroll
    for (int dy = 0; dy < 32; dy += 8)
        t[ty + dy][tx] = f[(size_t)b * CH * NP + (size_t)(c0 + ty + dy) * NP + n0 + tx];
    __syncthreads();
#pragma unroll
    for (int dy = 0; dy < 32; dy += 8)
        ft[(size_t)b * NP * CH + (size_t)(n0 + ty + dy) * CH + c0 + tx] = t[tx][ty + dy];
}

// ---------------- C=3 knn with queued (deferred) inserts (round-16 proven) ----------------
__global__ __launch_bounds__(128)
void knn3_kernel(const float* __restrict__ f, const float* __restrict__ xx,
                 int* __restrict__ idxout) {
    const int TQ = 128;
    const int CP = 4;
    __shared__ float smc[TQ * CP];
    __shared__ float smxx[TQ];
    __shared__ float sqd[128 * QCAP];
    __shared__ int   sqi[128 * QCAP];
    int b = blockIdx.y;
    int n = blockIdx.x * TQ + threadIdx.x;
    const float* fb = f + (size_t)b * 3 * NP;
    const int qbase = threadIdx.x * QCAP;

    float q0 = fb[n], q1 = fb[NP + n], q2 = fb[2 * NP + n];

    float vals[KNN];
    int   inds[KNN];
#pragma unroll
    for (int k = 0; k < KNN; k++) { vals[k] = -3.4e38f; inds[k] = 0; }
    float minv = -3.4e38f;
    int qn = 0;

    for (int m0 = 0; m0 < NP; m0 += TQ) {
        __syncthreads();
        for (int i = threadIdx.x; i < TQ * 3; i += TQ) {
            int c = i / TQ, j = i % TQ;
            smc[j * CP + c] = fb[(size_t)c * NP + m0 + j];
        }
        smxx[threadIdx.x] = xx[b * NP + m0 + threadIdx.x];
        __syncthreads();

        for (int j = 0; j < TQ; j += 2) {
            const float* c0 = &smc[j * CP];
            const float* c1 = &smc[(j + 1) * CP];
            float d0 = 2.f * (q0*c0[0] + q1*c0[1] + q2*c0[2]) - smxx[j];
            float d1 = 2.f * (q0*c1[0] + q1*c1[1] + q2*c1[2]) - smxx[j + 1];
            if (d0 > minv) { sqd[qbase + qn] = d0; sqi[qbase + qn] = m0 + j;     qn++; }
            if (d1 > minv) { sqd[qbase + qn] = d1; sqi[qbase + qn] = m0 + j + 1; qn++; }
            if (__ballot_sync(0xffffffffu, qn >= QCAP - 2)) {
                for (int e = 0; e < qn; e++) {
                    float v = sqd[qbase + e];
                    if (v > minv) {
                        BUBBLE_INSERT(v, sqi[qbase + e]);
                        minv = vals[KNN - 1];
                    }
                }
                qn = 0;
            }
        }
    }
    for (int e = 0; e < qn; e++) {
        float v = sqd[qbase + e];
        if (v > minv) { BUBBLE_INSERT(v, sqi[qbase + e]); minv = vals[KNN - 1]; }
    }
    int* op = idxout + ((size_t)b * NP + n) * KNN;
#pragma unroll
    for (int k = 0; k < KNN; k++) op[k] = inds[k];
}

// ---------------- C=64 knn: f32x2 dots (4-wide ILP) + warm gate + queued inserts ----------------
__global__ __launch_bounds__(64)
void knn64_kernel(const float* __restrict__ ft, const float* __restrict__ xx,
                  const int* __restrict__ prev, int* __restrict__ idxout) {
    const int TQ = 64;
    const int CP = CH + 4;
    __shared__ __align__(16) float smc[TQ * CP];
    __shared__ float smxx[TQ];
    __shared__ float sqd[64 * QC64];
    __shared__ int   sqi[64 * QC64];

    int b = blockIdx.y;
    int n = blockIdx.x * TQ + threadIdx.x;
    const float* ftb = ft + (size_t)b * NP * CH;
    const float* xxb = xx + b * NP;
    const int qbase = threadIdx.x * QC64;

    ull qp[CH / 2];
    {
        const ulonglong2* qs = (const ulonglong2*)(ftb + (size_t)n * CH);
#pragma unroll
        for (int i = 0; i < CH / 4; i++) { ulonglong2 t = qs[i]; qp[2*i] = t.x; qp[2*i+1] = t.y; }
    }

    float vals[KNN];
    int   inds[KNN];
#pragma unroll
    for (int k = 0; k < KNN; k++) { vals[k] = -3.4e38f; inds[k] = 0; }

    // warm start: tau = min over prev-layer neighbors' distances (exact lower bound)
    float tau = 3.4e38f;
    {
        const int* pi = prev + ((size_t)b * NP + n) * KNN;
#pragma unroll 4
        for (int k = 0; k < KNN; k++) {
            int m = pi[k];
            const ulonglong2* cs = (const ulonglong2*)(ftb + (size_t)m * CH);
            ull a0 = 0ull, a1 = 0ull;
#pragma unroll
            for (int i = 0; i < CH / 4; i++) {
                ulonglong2 t = cs[i];
                FMA_F32X2(a0, qp[2*i],   t.x, a0);
                FMA_F32X2(a1, qp[2*i+1], t.y, a1);
            }
            float d = 2.f * (f32x2_hsum(a0) + f32x2_hsum(a1)) - xxb[m];
            tau = fminf(tau, d);
        }
    }
    const float gate = tau - fabsf(tau) * 1e-4f - 1e-12f;
    float minv = gate;
    int qn = 0;

    for (int m0 = 0; m0 < NP; m0 += TQ) {
        __syncthreads();
        for (int i = threadIdx.x; i < TQ * (CH / 4); i += 64) {
            int j = i >> 4, c4 = i & 15;
            ((float4*)&smc[j * CP])[c4] = ((const float4*)(ftb + (size_t)(m0 + j) * CH))[c4];
        }
        smxx[threadIdx.x] = xxb[m0 + threadIdx.x];
        __syncthreads();

        for (int j = 0; j < TQ; j += 4) {
            const ulonglong2* c0 = (const ulonglong2*)&smc[j * CP];
            const ulonglong2* c1 = (const ulonglong2*)&smc[(j + 1) * CP];
            const ulonglong2* c2 = (const ulonglong2*)&smc[(j + 2) * CP];
            const ulonglong2* c3 = (const ulonglong2*)&smc[(j + 3) * CP];
            ull a00 = 0ull, a01 = 0ull, a10 = 0ull, a11 = 0ull;
            ull a20 = 0ull, a21 = 0ull, a30 = 0ull, a31 = 0ull;
#pragma unroll
            for (int i = 0; i < CH / 4; i++) {
                ulonglong2 t0 = c0[i], t1 = c1[i], t2 = c2[i], t3 = c3[i];
                FMA_F32X2(a00, qp[2*i],   t0.x, a00);
                FMA_F32X2(a01, qp[2*i+1], t0.y, a01);
                FMA_F32X2(a10, qp[2*i],   t1.x, a10);
                FMA_F32X2(a11, qp[2*i+1], t1.y, a11);
                FMA_F32X2(a20, qp[2*i],   t2.x, a20);
                FMA_F32X2(a21, qp[2*i+1], t2.y, a21);
                FMA_F32X2(a30, qp[2*i],   t3.x, a30);
                FMA_F32X2(a31, qp[2*i+1], t3.y, a31);
            }
            float d0 = 2.f * (f32x2_hsum(a00) + f32x2_hsum(a01)) - smxx[j];
            float d1 = 2.f * (f32x2_hsum(a10) + f32x2_hsum(a11)) - smxx[j + 1];
            float d2 = 2.f * (f32x2_hsum(a20) + f32x2_hsum(a21)) - smxx[j + 2];
            float d3 = 2.f * (f32x2_hsum(a30) + f32x2_hsum(a31)) - smxx[j + 3];
            if (d0 > minv) { sqd[qbase + qn] = d0; sqi[qbase + qn] = m0 + j;     qn++; }
            if (d1 > minv) { sqd[qbase + qn] = d1; sqi[qbase + qn] = m0 + j + 1; qn++; }
            if (d2 > minv) { sqd[qbase + qn] = d2; sqi[qbase + qn] = m0 + j + 2; qn++; }
            if (d3 > minv) { sqd[qbase + qn] = d3; sqi[qbase + qn] = m0 + j + 3; qn++; }
            if (__ballot_sync(0xffffffffu, qn >= QC64 - 4)) {
                for (int e = 0; e < qn; e++) {
                    float v = sqd[qbase + e];
                    if (v > minv) {
                        BUBBLE_INSERT(v, sqi[qbase + e]);
                        minv = fmaxf(vals[KNN - 1], gate);
                    }
                }
                qn = 0;
            }
        }
    }
    for (int e = 0; e < qn; e++) {
        float v = sqd[qbase + e];
        if (v > minv) { BUBBLE_INSERT(v, sqi[qbase + e]); minv = fmaxf(vals[KNN - 1], gate); }
    }
    int* op = idxout + ((size_t)b * NP + n) * KNN;
#pragma unroll
    for (int k = 0; k < KNN; k++) op[k] = inds[k];
}

// ---------------- point transform: A = Wl@f, Bt = (Wr-Wl)@f ----------------
template<int C>
__global__ void pt_kernel(const float* __restrict__ f, const float* __restrict__ Wa,
                          float* __restrict__ A, float* __restrict__ Bt) {
    int i = blockIdx.x * blockDim.x + threadIdx.x;
    if (i >= BB * CH * NP) return;
    int n = i % NP, o = (i / NP) % CH, b = i / (NP * CH);
    const float* fb = f + (size_t)b * C * NP + n;
    const float* w  = Wa + o * 2 * C;
    float a = 0.f, bm = 0.f;
#pragma unroll
    for (int c = 0; c < C; c++) {
        float v = fb[(size_t)c * NP];
        a  += w[c] * v;
        bm += (w[C + c] - w[c]) * v;
    }
    A[i] = a; Bt[i] = bm;
}

// ---------------- y1 gather + fused stats partials (proven win) ----------------
__global__ void y1_fused_kernel(const float* __restrict__ A, const float* __restrict__ Bt,
                                const int* __restrict__ idx, float* __restrict__ Y1,
                                float* __restrict__ ypart) {
    __shared__ float sA[NP];                    // 16 KB: full A plane for this (b,o)
    int bo = blockIdx.y;
    int b  = bo / CH;
    for (int i = threadIdx.x; i < NP; i += blockDim.x)
        sA[i] = A[(size_t)bo * NP + i];
    __syncthreads();
    int n0 = blockIdx.x * 512;
    const int*  ib = idx + ((size_t)b * NP + n0) * KNN;
    const float* bt = Bt + (size_t)bo * NP + n0;
    float* y = Y1 + ((size_t)bo * NP + n0) * KNN;
    float s = 0.f, s2 = 0.f;
    for (int i = threadIdx.x; i < 512 * KNN; i += blockDim.x) {
        int nl = i / KNN;
        float v = sA[ib[i]] + bt[nl];
        y[i] = v;
        s += v; s2 += v * v;
    }
    __shared__ float sh[512];
    sh[threadIdx.x] = s; sh[256 + threadIdx.x] = s2;
    __syncthreads();
    for (int st = 128; st > 0; st >>= 1) {
        if (threadIdx.x < st) {
            sh[threadIdx.x]       += sh[threadIdx.x + st];
            sh[256 + threadIdx.x] += sh[256 + threadIdx.x + st];
        }
        __syncthreads();
    }
    if (threadIdx.x == 0) {
        ypart[(bo * 8 + blockIdx.x) * 2]     = sh[0];
        ypart[(bo * 8 + blockIdx.x) * 2 + 1] = sh[256];
    }
}

// ---------------- finalize y1 stats: 8 partials -> (m, r) ----------------
__global__ void yfin_kernel(const float* __restrict__ ypart, float* __restrict__ stats) {
    int ch = blockIdx.x * blockDim.x + threadIdx.x;
    if (ch >= BB * CH) return;
    float s = 0.f, s2 = 0.f;
#pragma unroll
    for (int i = 0; i < 8; i++) {
        s  += ypart[(ch * 8 + i) * 2];
        s2 += ypart[(ch * 8 + i) * 2 + 1];
    }
    const float P = (float)(NP * KNN);
    float m = s / P;
    float var = s2 / P - m * m;
    stats[ch * 2]     = m;
    stats[ch * 2 + 1] = rsqrtf(var + CEPS);
}

// ---------------- conv2: round-9 structure, f32x2-packed inner loop ----------------
// acc pairs cover adjacent output channels; sWt rows reinterpreted as ulonglong2
// give exactly the (w_{2u}, w_{2u+1}) pairs. fp32 lane math is bitwise identical.
__global__ __launch_bounds__(128)
void conv2_kernel(const float* __restrict__ Y1, const float* __restrict__ Wb,
                  const float* __restrict__ stats, float* __restrict__ Y2) {
    const int P = NP * KNN;
    __shared__ __align__(16) float sWt[CH * CH];      // transposed: [c][o]
    __shared__ float sm[CH], sr[CH];
    int b = blockIdx.y;
    for (int i = threadIdx.x; i < CH * CH; i += 128) {
        int c = i >> 6, o = i & 63;
        sWt[c * CH + o] = Wb[o * CH + c];
    }
    if (threadIdx.x < CH) {
        sm[threadIdx.x] = stats[(b * CH + threadIdx.x) * 2];
        sr[threadIdx.x] = stats[(b * CH + threadIdx.x) * 2 + 1];
    }
    __syncthreads();
    int p0 = blockIdx.x * 256 + threadIdx.x;
    int p1 = p0 + 128;
    ull acc0[CH / 2], acc1[CH / 2];
#pragma unroll
    for (int u = 0; u < CH / 2; u++) { acc0[u] = 0ull; acc1[u] = 0ull; }
    const float* y1 = Y1 + (size_t)b * CH * P;
#pragma unroll 2
    for (int c = 0; c < CH; c++) {
        float v0 = y1[(size_t)c * P + p0];
        float v1 = y1[(size_t)c * P + p1];
        float m = sm[c], r = sr[c];
        v0 = (v0 - m) * r; v0 = v0 > 0.f ? v0 : 0.2f * v0;
        v1 = (v1 - m) * r; v1 = v1 > 0.f ? v1 : 0.2f * v1;
        ull v00, v11;
        PACK2(v00, v0); PACK2(v11, v1);
        const ulonglong2* w = (const ulonglong2*)&sWt[c * CH];
#pragma unroll
        for (int o4 = 0; o4 < 16; o4++) {
            ulonglong2 wp = w[o4];
            FMA_F32X2(acc0[2*o4],     wp.x, v00, acc0[2*o4]);
            FMA_F32X2(acc0[2*o4 + 1], wp.y, v00, acc0[2*o4 + 1]);
            FMA_F32X2(acc1[2*o4],     wp.x, v11, acc1[2*o4]);
            FMA_F32X2(acc1[2*o4 + 1], wp.y, v11, acc1[2*o4 + 1]);
        }
    }
    float* y2 = Y2 + (size_t)b * CH * P;
#pragma unroll
    for (int u = 0; u < CH / 2; u++) {
        float a, bb2, c2, d2;
        UNPACK2(a, bb2, acc0[u]);
        UNPACK2(c2, d2, acc1[u]);
        y2[(size_t)(2*u)     * P + p0] = a;
        y2[(size_t)(2*u + 1) * P + p0] = bb2;
        y2[(size_t)(2*u)     * P + p1] = c2;
        y2[(size_t)(2*u + 1) * P + p1] = d2;
    }
}

// ---------------- maxk_fused: one pass over Y2 -> raw max + stats partials ----------------
__global__ __launch_bounds__(256)
void maxk_fused_kernel(const float* __restrict__ Y2, float* __restrict__ mxraw,
                       float* __restrict__ mpart) {
    int i = blockIdx.x * 256 + threadIdx.x;          // over B*CH*NP
    const float4* y = (const float4*)(Y2 + (size_t)i * KNN);
    float mx = -3.4e38f, s = 0.f, s2 = 0.f;
#pragma unroll
    for (int k4 = 0; k4 < 5; k4++) {
        float4 v = y[k4];
        mx = fmaxf(mx, fmaxf(fmaxf(v.x, v.y), fmaxf(v.z, v.w)));
        s  += (v.x + v.y) + (v.z + v.w);
        s2 += (v.x * v.x + v.y * v.y) + (v.z * v.z + v.w * v.w);
    }
    mxraw[i] = mx;
    __shared__ float sh[512];
    sh[threadIdx.x] = s; sh[256 + threadIdx.x] = s2;
    __syncthreads();
    for (int st = 128; st > 0; st >>= 1) {
        if (threadIdx.x < st) {
            sh[threadIdx.x]       += sh[threadIdx.x + st];
            sh[256 + threadIdx.x] += sh[256 + threadIdx.x + st];
        }
        __syncthreads();
    }
    if (threadIdx.x == 0) {
        mpart[blockIdx.x * 2]     = sh[0];
        mpart[blockIdx.x * 2 + 1] = sh[256];
    }
}

// ---------------- finalize maxk stats: 16 partials -> (m, r) ----------------
__global__ void mfin_kernel(const float* __restrict__ mpart, float* __restrict__ stats) {
    int ch = blockIdx.x * blockDim.x + threadIdx.x;
    if (ch >= BB * CH) return;
    float s = 0.f, s2 = 0.f;
#pragma unroll
    for (int i = 0; i < 16; i++) {
        s  += mpart[(ch * 16 + i) * 2];
        s2 += mpart[(ch * 16 + i) * 2 + 1];
    }
    const float P = (float)(NP * KNN);
    float m = s / P;
    float var = s2 / P - m * m;
    stats[ch * 2]     = m;
    stats[ch * 2 + 1] = rsqrtf(var + CEPS);
}

// ---------------- apply inorm+lrelu to the raw maxes (max commutes, r>0) ----------------
__global__ void apply_kernel(const float* __restrict__ mxraw, const float* __restrict__ stats,
                             float* __restrict__ xout) {
    int i = blockIdx.x * blockDim.x + threadIdx.x;
    if (i >= BB * CH * NP) return;
    int bo = i / NP;
    float m = stats[bo * 2], r = stats[bo * 2 + 1];
    float v = (mxraw[i] - m) * r;
    v = v > 0.f ? v : 0.2f * v;
    xout[i] = v;
}

// ---------------- final GEMM, f32x2-packed inner loop; writes Y ----------------
__global__ __launch_bounds__(128)
void fgemm_kernel(const float* __restrict__ x1, const float* __restrict__ x2,
                  const float* __restrict__ x3, const float* __restrict__ Ws,
                  float* __restrict__ Y) {
    __shared__ __align__(16) float sWt[192 * 64];     // transposed [c][o], 48 KB
    int b  = blockIdx.z;
    int o0 = blockIdx.y * 64;
    int n0 = blockIdx.x * 256 + threadIdx.x;
    int n1 = n0 + 128;
    for (int i = threadIdx.x; i < 192 * 64; i += 128) {
        int c = i >> 6, o = i & 63;
        sWt[c * 64 + o] = Ws[(size_t)(o0 + o) * 192 + c];
    }
    __syncthreads();
    ull acc0[32], acc1[32];
#pragma unroll
    for (int u = 0; u < 32; u++) { acc0[u] = 0ull; acc1[u] = 0ull; }
    const float* srcs[3] = { x1 + (size_t)b * CH * NP,
                             x2 + (size_t)b * CH * NP,
                             x3 + (size_t)b * CH * NP };
    for (int g = 0; g < 3; g++) {
        const float* s = srcs[g];
#pragma unroll 2
        for (int c = 0; c < 64; c++) {
            float v0 = s[(size_t)c * NP + n0];
            float v1 = s[(size_t)c * NP + n1];
            ull v00, v11;
            PACK2(v00, v0); PACK2(v11, v1);
            const ulonglong2* w = (const ulonglong2*)&sWt[(g * 64 + c) * 64];
#pragma unroll
            for (int o4 = 0; o4 < 16; o4++) {
                ulonglong2 wp = w[o4];
                FMA_F32X2(acc0[2*o4],     wp.x, v00, acc0[2*o4]);
                FMA_F32X2(acc0[2*o4 + 1], wp.y, v00, acc0[2*o4 + 1]);
                FMA_F32X2(acc1[2*o4],     wp.x, v11, acc1[2*o4]);
                FMA_F32X2(acc1[2*o4 + 1], wp.y, v11, acc1[2*o4 + 1]);
            }
        }
    }
    float* y = Y + ((size_t)b * 1024 + o0) * NP;
#pragma unroll
    for (int u = 0; u < 32; u++) {
        float a, bb2, c2, d2;
        UNPACK2(a, bb2, acc0[u]);
        UNPACK2(c2, d2, acc1[u]);
        y[(size_t)(2*u)     * NP + n0] = a;
        y[(size_t)(2*u + 1) * NP + n0] = bb2;
        y[(size_t)(2*u)     * NP + n1] = c2;
        y[(size_t)(2*u + 1) * NP + n1] = d2;
    }
}

// ---------------- fused head stats+pool: one block per (b,ch), single read of Y ----------------
__global__ __launch_bounds__(128)
void statspool_kernel(const float* __restrict__ Y, float* __restrict__ pool) {
    int ch = blockIdx.x;            // b*1024 + o
    const float4* y = (const float4*)(Y + (size_t)ch * NP);
    float s = 0.f, s2 = 0.f, mx = -3.4e38f;
    for (int i = threadIdx.x; i < NP / 4; i += 128) {
        float4 v = y[i];
        s  += (v.x + v.y) + (v.z + v.w);
        s2 += (v.x * v.x + v.y * v.y) + (v.z * v.z + v.w * v.w);
        mx  = fmaxf(mx, fmaxf(fmaxf(v.x, v.y), fmaxf(v.z, v.w)));
    }
    __shared__ float sh[384];
    sh[threadIdx.x] = s; sh[128 + threadIdx.x] = s2; sh[256 + threadIdx.x] = mx;
    __syncthreads();
    for (int st = 64; st > 0; st >>= 1) {
        if (threadIdx.x < st) {
            sh[threadIdx.x]       += sh[threadIdx.x + st];
            sh[128 + threadIdx.x] += sh[128 + threadIdx.x + st];
            sh[256 + threadIdx.x]  = fmaxf(sh[256 + threadIdx.x], sh[256 + threadIdx.x + st]);
        }
        __syncthreads();
    }
    if (threadIdx.x == 0) {
        float m   = sh[0] / (float)NP;
        float var = sh[128] / (float)NP - m * m;
        float r   = rsqrtf(var + CEPS);
        float v = (sh[256] - m) * r;   // max commutes with monotone affine map (r>0)
        v = v > 0.f ? v : 0.2f * v;
        pool[ch] = v;
    }
}

// ---------------- assemble output: [pool bcast | x1 | x2 | x3] ----------------
__global__ void out_kernel(const float* __restrict__ pool, const float* __restrict__ x1,
                           const float* __restrict__ x2, const float* __restrict__ x3,
                           float* __restrict__ out) {
    size_t i = (size_t)blockIdx.x * blockDim.x + threadIdx.x;
    const size_t total = (size_t)BB * 1216 * NP;
    if (i >= total) return;
    int n  = (int)(i % NP);
    int ch = (int)((i / NP) % 1216);
    int b  = (int)(i / ((size_t)NP * 1216));
    float v;
    if (ch < 1024) {
        v = pool[b * 1024 + ch];
    } else {
        int c2 = ch - 1024;
        const float* s = (c2 < 64) ? x1 : (c2 < 128 ? x2 : x3);
        v = s[((size_t)b * CH + (c2 & 63)) * NP + n];
    }
    out[i] = v;
}

// ---------------- conv tail shared by all layers ----------------
static void run_conv_tail(const float* Wb, const int* idxp, float* Ap, float* Btp,
                          float* Y1p, float* Y2p, float* stp, float* ypartp,
                          float* mpartp, float* mxp, float* xout) {
    y1_fused_kernel<<<dim3(NP / 512, BB * CH), 256>>>(Ap, Btp, idxp, Y1p, ypartp);
    yfin_kernel<<<2, 256>>>(ypartp, stp);
    conv2_kernel<<<dim3(NP * KNN / 256, BB), 128>>>(Y1p, Wb, stp, Y2p);
    maxk_fused_kernel<<<BB * CH * NP / 256, 256>>>(Y2p, mxp, mpartp);
    mfin_kernel<<<2, 256>>>(mpartp, stp);
    apply_kernel<<<(BB * CH * NP + 255) / 256, 256>>>(mxp, stp, xout);
}

extern "C" void kernel_launch(void* const* d_in, const int* in_sizes, int n_in,
                              void* d_out, int out_size) {
    const float* x   = (const float*)d_in[0];
    const float* W0a = (const float*)d_in[1];
    const float* W0b = (const float*)d_in[2];
    const float* W1a = (const float*)d_in[3];
    const float* W1b = (const float*)d_in[4];
    const float* W2a = (const float*)d_in[5];
    const float* W2b = (const float*)d_in[6];
    const float* Ws  = (const float*)d_in[7];
    float* out = (float*)d_out;

    float *xxp, *ftp, *Ap, *Btp, *Y1p, *Y2p, *mxp, *x1p, *x2p, *x3p, *stp;
    float *ypartp, *mpartp, *Yp, *poolp;
    int *idxAp, *idxBp;
    cudaGetSymbolAddress((void**)&xxp,    g_xx);
    cudaGetSymbolAddress((void**)&idxAp,  g_idxA);
    cudaGetSymbolAddress((void**)&idxBp,  g_idxB);
    cudaGetSymbolAddress((void**)&ftp,    g_ft);
    cudaGetSymbolAddress((void**)&Ap,     g_A);
    cudaGetSymbolAddress((void**)&Btp,    g_Bt);
    cudaGetSymbolAddress((void**)&Y1p,    g_Y1);
    cudaGetSymbolAddress((void**)&Y2p,    g_Y2);
    cudaGetSymbolAddress((void**)&mxp,    g_mx);
    cudaGetSymbolAddress((void**)&x1p,    g_x1);
    cudaGetSymbolAddress((void**)&x2p,    g_x2);
    cudaGetSymbolAddress((void**)&x3p,    g_x3);
    cudaGetSymbolAddress((void**)&stp,    g_st);
    cudaGetSymbolAddress((void**)&ypartp, g_ypart);
    cudaGetSymbolAddress((void**)&mpartp, g_mpart);
    cudaGetSymbolAddress((void**)&Yp,     g_Y);
    cudaGetSymbolAddress((void**)&poolp,  g_pool);

    // ---- layer 0 (C=3): knn on raw coords -> idxA ----
    xx_kernel<3><<<(BB * NP + 255) / 256, 256>>>(x, xxp);
    knn3_kernel<<<dim3(NP / 128, BB), 128>>>(x, xxp, idxAp);
    pt_kernel<3><<<(BB * CH * NP + 255) / 256, 256>>>(x, W0a, Ap, Btp);
    run_conv_tail(W0b, idxAp, Ap, Btp, Y1p, Y2p, stp, ypartp, mpartp, mxp, x1p);

    // ---- layer 1 (C=64): knn on x1, warm from idxA -> idxB ----
    xx_kernel<CH><<<(BB * NP + 255) / 256, 256>>>(x1p, xxp);
    transpose_kernel<<<dim3(NP / 32, CH / 32, BB), dim3(32, 8)>>>(x1p, ftp);
    knn64_kernel<<<dim3(NP / 64, BB), 64>>>(ftp, xxp, idxAp, idxBp);
    pt_kernel<CH><<<(BB * CH * NP + 255) / 256, 256>>>(x1p, W1a, Ap, Btp);
    run_conv_tail(W1b, idxBp, Ap, Btp, Y1p, Y2p, stp, ypartp, mpartp, mxp, x2p);

    // ---- layer 2 (C=64): knn on x2, warm from idxB -> idxA ----
    xx_kernel<CH><<<(BB * NP + 255) / 256, 256>>>(x2p, xxp);
    transpose_kernel<<<dim3(NP / 32, CH / 32, BB), dim3(32, 8)>>>(x2p, ftp);
    knn64_kernel<<<dim3(NP / 64, BB), 64>>>(ftp, xxp, idxBp, idxAp);
    pt_kernel<CH><<<(BB * CH * NP + 255) / 256, 256>>>(x2p, W2a, Ap, Btp);
    run_conv_tail(W2b, idxAp, Ap, Btp, Y1p, Y2p, stp, ypartp, mpartp, mxp, x3p);

    // ---- head: fgemm (f32x2) -> fused stats+pool single pass ----
    fgemm_kernel<<<dim3(NP / 256, 1024 / 64, BB), 128>>>(x1p, x2p, x3p, Ws, Yp);
    statspool_kernel<<<BB * 1024, 128>>>(Yp, poolp);

    const size_t total = (size_t)BB * 1216 * NP;
    out_kernel<<<(unsigned)((total + 255) / 256), 256>>>(poolp, x1p, x2p, x3p, out);
}